// round 2
// baseline (speedup 1.0000x reference)
#include <cuda_runtime.h>
#include <cuda_bf16.h>
#include <stdint.h>

#define N_NODES 50000
#define F 256            // hidden == out features
#define NFEAT 1024
#define EPSV 1e-5f

// ---------------- scratch (__device__ globals; no allocation allowed) ----------------
__device__ float g_h1  [(size_t)N_NODES * F];
__device__ float g_agg1[(size_t)N_NODES * F];
__device__ float g_h2  [(size_t)N_NODES * F];
__device__ float g_agg2[(size_t)N_NODES * F];
__device__ float g_deg [N_NODES];
__device__ float g_dinv[N_NODES];
__device__ float g_bnsum[F];
__device__ float g_bnssq[F];
__device__ int   g_is64;

// ---------------- dtype detection for edge_index (int64 vs int32) ----------------
__global__ void detect_idx_dtype(const int* ei32, int n_check) {
    __shared__ int bad;
    if (threadIdx.x == 0) bad = 0;
    __syncthreads();
    for (int i = threadIdx.x; i < n_check; i += blockDim.x)
        if (ei32[2 * i + 1] != 0) bad = 1;
    __syncthreads();
    if (threadIdx.x == 0) g_is64 = bad ? 0 : 1;
}

__device__ __forceinline__ long ld_idx(const void* ei, long i) {
    return g_is64 ? (long)((const long long*)ei)[i] : (long)((const int*)ei)[i];
}

// ---------------- degree / norm ----------------
__global__ void init_deg(int n) {
    int i = blockIdx.x * blockDim.x + threadIdx.x;
    if (i < n) g_deg[i] = 1.0f;   // self-loop weight 1
}

__global__ void edge_deg(const void* ei, const float* w, long E) {
    long e = blockIdx.x * (long)blockDim.x + threadIdx.x;
    if (e >= E) return;
    long dst = ld_idx(ei, E + e);
    atomicAdd(&g_deg[dst], w[e]);
}

__global__ void compute_dinv(int n) {
    int i = blockIdx.x * blockDim.x + threadIdx.x;
    if (i < n) {
        float d = g_deg[i];
        g_dinv[i] = d > 0.0f ? rsqrtf(fmaxf(d, 1e-30f)) : 0.0f;
    }
}

// ---------------- tensor-core GEMM (bf16x3 split, fp32-accurate) ----------------
// C = A[M,K] @ B[K,N]; writes H = C and AGG = bias + dinv[row]^2 * C.
// A optionally relu'd on load. Block tile 128x128x32, 8 warps of 64x32.

__device__ __forceinline__ unsigned pk(__nv_bfloat16 lo, __nv_bfloat16 hi) {
    __nv_bfloat162 t = __halves2bfloat162(lo, hi);   // lo -> low 16 bits
    return *reinterpret_cast<unsigned*>(&t);
}

__device__ __forceinline__ void split2(float x, __nv_bfloat16& h, __nv_bfloat16& l) {
    h = __float2bfloat16_rn(x);
    l = __float2bfloat16_rn(x - __bfloat162float(h));
}

__device__ __forceinline__ void ldsm_x4(unsigned* r, const void* p) {
    unsigned a = (unsigned)__cvta_generic_to_shared(p);
    asm volatile("ldmatrix.sync.aligned.m8n8.x4.shared.b16 {%0,%1,%2,%3}, [%4];"
                 : "=r"(r[0]), "=r"(r[1]), "=r"(r[2]), "=r"(r[3]) : "r"(a));
}

__device__ __forceinline__ void ldsm_x4_t(unsigned* r, const void* p) {
    unsigned a = (unsigned)__cvta_generic_to_shared(p);
    asm volatile("ldmatrix.sync.aligned.m8n8.x4.trans.shared.b16 {%0,%1,%2,%3}, [%4];"
                 : "=r"(r[0]), "=r"(r[1]), "=r"(r[2]), "=r"(r[3]) : "r"(a));
}

__device__ __forceinline__ void mma_bf16(float* d, const unsigned* a, const unsigned* b) {
    asm volatile(
        "mma.sync.aligned.m16n8k16.row.col.f32.bf16.bf16.f32 "
        "{%0,%1,%2,%3}, {%4,%5,%6,%7}, {%8,%9}, {%0,%1,%2,%3};"
        : "+f"(d[0]), "+f"(d[1]), "+f"(d[2]), "+f"(d[3])
        : "r"(a[0]), "r"(a[1]), "r"(a[2]), "r"(a[3]), "r"(b[0]), "r"(b[1]));
}

template <bool RELU>
__global__ __launch_bounds__(256, 1) void gemm_bf16x3(
    int M, int N, int K,
    const float* __restrict__ A, const float* __restrict__ B,
    const float* __restrict__ bias,
    float* __restrict__ H, float* __restrict__ AGG)
{
    const int ASTR = 40;    // bf16 elems per A smem row (32 + 8 pad) — conflict-free
    const int BSTR = 136;   // bf16 elems per B smem row (128 + 8 pad) — conflict-free
    __shared__ unsigned short Ah[128 * ASTR], Al[128 * ASTR];
    __shared__ unsigned short Bh[32 * BSTR],  Bl[32 * BSTR];

    const int tid = threadIdx.x, lane = tid & 31, warp = tid >> 5;
    const int wm = warp >> 2, wn = warp & 3;          // 2 x 4 warp grid
    const int bRow = blockIdx.x, bCol = blockIdx.y;

    // gmem load coords
    const int arow0 = tid >> 3;           // 0..31
    const int acol0 = (tid & 7) * 4;      // 0..28
    const int brow0 = tid >> 5;           // 0..7
    const int bcol0 = (tid & 31) * 4;     // 0..124

    float4 aReg[4], bReg[4];
    const int nk = K / 32;

    auto LDG = [&](int kb) {
#pragma unroll
        for (int i = 0; i < 4; i++) {
            int gr = bRow * 128 + arow0 + 32 * i;
            aReg[i] = (gr < M) ? *(const float4*)(A + (size_t)gr * K + kb * 32 + acol0)
                               : make_float4(0.f, 0.f, 0.f, 0.f);
        }
#pragma unroll
        for (int i = 0; i < 4; i++) {
            int gk = kb * 32 + brow0 + 8 * i;
            bReg[i] = *(const float4*)(B + (size_t)gk * N + bCol * 128 + bcol0);
        }
    };

    float acc[4][4][4];
#pragma unroll
    for (int mi = 0; mi < 4; mi++)
#pragma unroll
        for (int nj = 0; nj < 4; nj++)
#pragma unroll
            for (int r = 0; r < 4; r++) acc[mi][nj][r] = 0.f;

    LDG(0);

    const int g8  = lane & 7;
    const int m01 = (lane >> 3) & 1;
    const int m23 = lane >> 4;

    for (int kb = 0; kb < nk; kb++) {
        __syncthreads();   // previous compute done reading smem
        // ---- convert + store current tile ----
#pragma unroll
        for (int i = 0; i < 4; i++) {
            int row = arow0 + 32 * i;
            float4 v = aReg[i];
            if (RELU) {
                v.x = fmaxf(v.x, 0.f); v.y = fmaxf(v.y, 0.f);
                v.z = fmaxf(v.z, 0.f); v.w = fmaxf(v.w, 0.f);
            }
            __nv_bfloat16 h0, l0, h1, l1, h2, l2, h3, l3;
            split2(v.x, h0, l0); split2(v.y, h1, l1);
            split2(v.z, h2, l2); split2(v.w, h3, l3);
            unsigned* ph = (unsigned*)&Ah[row * ASTR + acol0];
            unsigned* pl = (unsigned*)&Al[row * ASTR + acol0];
            ph[0] = pk(h0, h1); ph[1] = pk(h2, h3);
            pl[0] = pk(l0, l1); pl[1] = pk(l2, l3);
        }
#pragma unroll
        for (int i = 0; i < 4; i++) {
            int krow = brow0 + 8 * i;
            float4 v = bReg[i];
            __nv_bfloat16 h0, l0, h1, l1, h2, l2, h3, l3;
            split2(v.x, h0, l0); split2(v.y, h1, l1);
            split2(v.z, h2, l2); split2(v.w, h3, l3);
            unsigned* ph = (unsigned*)&Bh[krow * BSTR + bcol0];
            unsigned* pl = (unsigned*)&Bl[krow * BSTR + bcol0];
            ph[0] = pk(h0, h1); ph[1] = pk(h2, h3);
            pl[0] = pk(l0, l1); pl[1] = pk(l2, l3);
        }
        __syncthreads();

        if (kb + 1 < nk) LDG(kb + 1);   // prefetch next tile into regs

        // ---- compute over current smem tile ----
#pragma unroll
        for (int kk = 0; kk < 2; kk++) {
            const int k0 = kk * 16;
            unsigned aFh[4][4], aFl[4][4], bFh[4][2], bFl[4][2];
#pragma unroll
            for (int mi = 0; mi < 4; mi++) {
                int row = wm * 64 + mi * 16 + g8 + m01 * 8;
                int kof = k0 + m23 * 8;
                ldsm_x4(aFh[mi], &Ah[row * ASTR + kof]);
                ldsm_x4(aFl[mi], &Al[row * ASTR + kof]);
            }
#pragma unroll
            for (int bj = 0; bj < 2; bj++) {
                int krow = k0 + g8 + m01 * 8;
                int ncol = wn * 32 + bj * 16 + m23 * 8;
                unsigned t[4];
                ldsm_x4_t(t, &Bh[krow * BSTR + ncol]);
                bFh[2 * bj][0] = t[0]; bFh[2 * bj][1] = t[1];
                bFh[2 * bj + 1][0] = t[2]; bFh[2 * bj + 1][1] = t[3];
                ldsm_x4_t(t, &Bl[krow * BSTR + ncol]);
                bFl[2 * bj][0] = t[0]; bFl[2 * bj][1] = t[1];
                bFl[2 * bj + 1][0] = t[2]; bFl[2 * bj + 1][1] = t[3];
            }
#pragma unroll
            for (int mi = 0; mi < 4; mi++)
#pragma unroll
                for (int nj = 0; nj < 4; nj++) {
                    mma_bf16(acc[mi][nj], aFh[mi], bFh[nj]);
                    mma_bf16(acc[mi][nj], aFh[mi], bFl[nj]);
                    mma_bf16(acc[mi][nj], aFl[mi], bFh[nj]);
                }
        }
    }

    // ---- epilogue: H = acc ; AGG = bias + dinv^2 * acc ----
    const int gg = lane >> 2, cc = lane & 3;
#pragma unroll
    for (int mi = 0; mi < 4; mi++) {
        int rb = bRow * 128 + wm * 64 + mi * 16;
        int r0 = rb + gg, r1 = rb + gg + 8;
        float di0 = (r0 < M) ? g_dinv[r0] : 0.f;
        float di1 = (r1 < M) ? g_dinv[r1] : 0.f;
        float s0 = di0 * di0, s1 = di1 * di1;
#pragma unroll
        for (int nj = 0; nj < 4; nj++) {
            int col = bCol * 128 + wn * 32 + nj * 8 + 2 * cc;
            float b0 = bias[col], b1 = bias[col + 1];
            float* a = acc[mi][nj];
            if (r0 < M) {
                float2 hv = make_float2(a[0], a[1]);
                *(float2*)(H + (size_t)r0 * N + col) = hv;
                *(float2*)(AGG + (size_t)r0 * N + col) =
                    make_float2(b0 + s0 * a[0], b1 + s0 * a[1]);
            }
            if (r1 < M) {
                float2 hv = make_float2(a[2], a[3]);
                *(float2*)(H + (size_t)r1 * N + col) = hv;
                *(float2*)(AGG + (size_t)r1 * N + col) =
                    make_float2(b0 + s1 * a[2], b1 + s1 * a[3]);
            }
        }
    }
}

// ---------------- edge aggregation ----------------
// one warp per edge: agg[dst,:] += dinv[src]*w*dinv[dst] * h[src,:]
__global__ void edge_agg(const void* __restrict__ ei, const float* __restrict__ w,
                         const float* __restrict__ h, float* __restrict__ agg, long E) {
    long warp = (blockIdx.x * (long)blockDim.x + threadIdx.x) >> 5;
    int  lane = threadIdx.x & 31;
    if (warp >= E) return;
    long src = ld_idx(ei, warp);
    long dst = ld_idx(ei, E + warp);
    float nw = g_dinv[src] * w[warp] * g_dinv[dst];
    const float4* hs = (const float4*)(h + src * F);
    float* ad = agg + dst * F;
    float4 v0 = hs[lane];
    float4 v1 = hs[lane + 32];
    atomicAdd(ad + 4 * lane + 0,   nw * v0.x);
    atomicAdd(ad + 4 * lane + 1,   nw * v0.y);
    atomicAdd(ad + 4 * lane + 2,   nw * v0.z);
    atomicAdd(ad + 4 * lane + 3,   nw * v0.w);
    atomicAdd(ad + 4 * lane + 128, nw * v1.x);
    atomicAdd(ad + 4 * lane + 129, nw * v1.y);
    atomicAdd(ad + 4 * lane + 130, nw * v1.z);
    atomicAdd(ad + 4 * lane + 131, nw * v1.w);
}

// ---------------- batchnorm stats over relu(agg2) ----------------
__global__ void bn_zero() {
    int f = threadIdx.x;
    g_bnsum[f] = 0.0f;
    g_bnssq[f] = 0.0f;
}

__global__ void bn_stats(const float* __restrict__ agg2, int M, int rows_per_block) {
    int f = threadIdx.x;
    long r0 = blockIdx.x * (long)rows_per_block;
    long r1 = r0 + rows_per_block; if (r1 > M) r1 = M;
    float s = 0.f, ss = 0.f;
    for (long r = r0; r < r1; r++) {
        float v = fmaxf(agg2[r * F + f], 0.f);
        s += v; ss += v * v;
    }
    atomicAdd(&g_bnsum[f], s);
    atomicAdd(&g_bnssq[f], ss);
}

// ---------------- fused relu + BN + LN epilogue ----------------
__global__ void bn_ln_final(const float* __restrict__ agg2,
                            const float* __restrict__ bg, const float* __restrict__ bb,
                            const float* __restrict__ lg, const float* __restrict__ lb,
                            float* __restrict__ out, int M) {
    long r = blockIdx.x;
    int  f = threadIdx.x;
    int  lane = f & 31, wid = f >> 5;
    float invM = 1.0f / (float)M;

    float mu  = g_bnsum[f] * invM;
    float var = g_bnssq[f] * invM - mu * mu;
    float v = fmaxf(agg2[r * F + f], 0.f);
    float y = (v - mu) * rsqrtf(var + EPSV) * bg[f] + bb[f];

    float s = y, ss = y * y;
#pragma unroll
    for (int o = 16; o > 0; o >>= 1) {
        s  += __shfl_xor_sync(0xffffffffu, s,  o);
        ss += __shfl_xor_sync(0xffffffffu, ss, o);
    }
    __shared__ float reds[8], redss[8];
    if (lane == 0) { reds[wid] = s; redss[wid] = ss; }
    __syncthreads();
    if (wid == 0) {
        float a = lane < 8 ? reds[lane]  : 0.f;
        float b = lane < 8 ? redss[lane] : 0.f;
#pragma unroll
        for (int o = 4; o > 0; o >>= 1) {
            a += __shfl_xor_sync(0xffffffffu, a, o);
            b += __shfl_xor_sync(0xffffffffu, b, o);
        }
        if (lane == 0) { reds[0] = a; redss[0] = b; }
    }
    __syncthreads();
    float lmu  = reds[0]  * (1.0f / F);
    float lvar = redss[0] * (1.0f / F) - lmu * lmu;
    out[r * F + f] = (y - lmu) * rsqrtf(lvar + EPSV) * lg[f] + lb[f];
}

// ---------------- launcher ----------------
extern "C" void kernel_launch(void* const* d_in, const int* in_sizes, int n_in,
                              void* d_out, int out_size) {
    const float* x  = (const float*)d_in[0];
    const void*  ei = d_in[1];
    const float* ew = (const float*)d_in[2];
    const float* W1 = (const float*)d_in[3];
    const float* b1 = (const float*)d_in[4];
    const float* W2 = (const float*)d_in[5];
    const float* b2 = (const float*)d_in[6];
    const float* bg = (const float*)d_in[7];
    const float* bb = (const float*)d_in[8];
    const float* lg = (const float*)d_in[9];
    const float* lb = (const float*)d_in[10];
    float* out = (float*)d_out;

    int  n = in_sizes[0] / NFEAT;            // 50000
    long E = in_sizes[1] / 2;                // 800000

    float* h1;   cudaGetSymbolAddress((void**)&h1,   g_h1);
    float* agg1; cudaGetSymbolAddress((void**)&agg1, g_agg1);
    float* h2;   cudaGetSymbolAddress((void**)&h2,   g_h2);
    float* agg2; cudaGetSymbolAddress((void**)&agg2, g_agg2);

    // 0) edge_index dtype detection
    detect_idx_dtype<<<1, 256>>>((const int*)ei, 1024);

    // 1) degree + norm (must precede GEMM epilogues, which use dinv)
    init_deg<<<(n + 255) / 256, 256>>>(n);
    edge_deg<<<(int)((E + 255) / 256), 256>>>(ei, ew, E);
    compute_dinv<<<(n + 255) / 256, 256>>>(n);

    int edgeBlocks = (int)((E + 7) / 8);     // 8 warps/block, 1 warp/edge
    dim3 gg((n + 127) / 128, F / 128);

    // 2) layer 1: h1 = x @ W1 ; agg1 = b1 + dinv^2*h1 (epilogue) ; + edges
    gemm_bf16x3<false><<<gg, 256>>>(n, F, NFEAT, x, W1, b1, h1, agg1);
    edge_agg<<<edgeBlocks, 256>>>(ei, ew, h1, agg1, E);

    // 3) layer 2: h2 = relu(agg1) @ W2 ; agg2 = b2 + dinv^2*h2 ; + edges
    gemm_bf16x3<true><<<gg, 256>>>(n, F, F, agg1, W2, b2, h2, agg2);
    edge_agg<<<edgeBlocks, 256>>>(ei, ew, h2, agg2, E);

    // 4) BN stats over relu(agg2)
    bn_zero<<<1, F>>>();
    const int RPB = 128;
    bn_stats<<<(n + RPB - 1) / RPB, F>>>(agg2, n, RPB);

    // 5) fused relu + BN + LN
    bn_ln_final<<<n, F>>>(agg2, bg, bb, lg, lb, out, n);
}

// round 3
// speedup vs baseline: 1.9759x; 1.9759x over previous
#include <cuda_runtime.h>
#include <cuda_bf16.h>
#include <stdint.h>

#define N_NODES 50000
#define F 256
#define NFEAT 1024
#define E_MAX 800000
#define EPSV 1e-5f

// ---------------- scratch (__device__ globals) ----------------
__device__ float g_h1  [(size_t)N_NODES * F];
__device__ float g_agg1[(size_t)N_NODES * F];
__device__ float g_h2  [(size_t)N_NODES * F];
__device__ float g_agg2[(size_t)N_NODES * F];
__device__ __nv_bfloat16 g_xh[(size_t)N_NODES * NFEAT];
__device__ __nv_bfloat16 g_xl[(size_t)N_NODES * NFEAT];
__device__ __nv_bfloat16 g_a1h[(size_t)N_NODES * F];
__device__ __nv_bfloat16 g_a1l[(size_t)N_NODES * F];
__device__ __nv_bfloat16 g_w1h[NFEAT * F], g_w1l[NFEAT * F];
__device__ __nv_bfloat16 g_w2h[F * F],     g_w2l[F * F];
__device__ float g_deg [N_NODES];
__device__ float g_dinv[N_NODES];
__device__ int   g_counts [N_NODES];
__device__ int   g_offsets[N_NODES + 1];
__device__ int   g_cursor [N_NODES];
__device__ uint2 g_epack  [E_MAX];          // (src, norm-weight)
__device__ float g_bnsum[F];
__device__ float g_bnssq[F];
__device__ int   g_is64;

// ---------------- edge_index dtype detection ----------------
__global__ void detect_idx_dtype(const int* ei32, int n_check) {
    __shared__ int bad;
    if (threadIdx.x == 0) bad = 0;
    __syncthreads();
    for (int i = threadIdx.x; i < n_check; i += blockDim.x)
        if (ei32[2 * i + 1] != 0) bad = 1;
    __syncthreads();
    if (threadIdx.x == 0) g_is64 = bad ? 0 : 1;
}

__device__ __forceinline__ long ld_idx(const void* ei, long i) {
    return g_is64 ? (long)((const long long*)ei)[i] : (long)((const int*)ei)[i];
}

// ---------------- degree + CSR histogram ----------------
__global__ void zero_counts_deg(int n) {
    int i = blockIdx.x * blockDim.x + threadIdx.x;
    if (i < n) { g_counts[i] = 0; g_deg[i] = 1.0f; }   // self-loop weight 1
}

__global__ void histo_deg(const void* ei, const float* w, long E) {
    long e = blockIdx.x * (long)blockDim.x + threadIdx.x;
    if (e >= E) return;
    long dst = ld_idx(ei, E + e);
    atomicAdd(&g_deg[dst], w[e]);
    atomicAdd(&g_counts[(int)dst], 1);
}

__global__ void compute_dinv(int n) {
    int i = blockIdx.x * blockDim.x + threadIdx.x;
    if (i < n) {
        float d = g_deg[i];
        g_dinv[i] = d > 0.0f ? rsqrtf(fmaxf(d, 1e-30f)) : 0.0f;
    }
}

// single-block exclusive scan of counts -> offsets (and cursor copy)
__global__ __launch_bounds__(1024) void scan_offsets(int n) {
    __shared__ int ssum[1024];
    int t = threadIdx.x;
    int chunk = (n + 1023) / 1024;
    int beg = t * chunk, end = min(beg + chunk, n);
    int s = 0;
    for (int i = beg; i < end; i++) s += g_counts[i];
    ssum[t] = s;
    __syncthreads();
    for (int o = 1; o < 1024; o <<= 1) {
        int u = (t >= o) ? ssum[t - o] : 0;
        __syncthreads();
        ssum[t] += u;
        __syncthreads();
    }
    int run = ssum[t] - s;   // exclusive prefix for this thread's chunk
    for (int i = beg; i < end; i++) {
        g_offsets[i] = run;
        g_cursor[i]  = run;
        run += g_counts[i];
    }
    if (t == 1023) g_offsets[n] = run;
}

__global__ void scatter_edges(const void* ei, const float* w, long E) {
    long e = blockIdx.x * (long)blockDim.x + threadIdx.x;
    if (e >= E) return;
    long src = ld_idx(ei, e);
    long dst = ld_idx(ei, E + e);
    float nw = g_dinv[src] * w[e] * g_dinv[dst];
    int pos = atomicAdd(&g_cursor[(int)dst], 1);
    g_epack[pos] = make_uint2((unsigned)src, __float_as_uint(nw));
}

// ---------------- fp32 -> bf16 hi/lo split conversion ----------------
__device__ __forceinline__ unsigned pk(__nv_bfloat16 lo, __nv_bfloat16 hi) {
    __nv_bfloat162 t = __halves2bfloat162(lo, hi);
    return *reinterpret_cast<unsigned*>(&t);
}

__global__ void convert_split(const float* __restrict__ in,
                              __nv_bfloat16* __restrict__ hi,
                              __nv_bfloat16* __restrict__ lo,
                              long n4, int relu) {
    long i = blockIdx.x * (long)blockDim.x + threadIdx.x;
    if (i >= n4) return;
    float4 v = ((const float4*)in)[i];
    if (relu) {
        v.x = fmaxf(v.x, 0.f); v.y = fmaxf(v.y, 0.f);
        v.z = fmaxf(v.z, 0.f); v.w = fmaxf(v.w, 0.f);
    }
    __nv_bfloat16 h0 = __float2bfloat16_rn(v.x);
    __nv_bfloat16 h1 = __float2bfloat16_rn(v.y);
    __nv_bfloat16 h2 = __float2bfloat16_rn(v.z);
    __nv_bfloat16 h3 = __float2bfloat16_rn(v.w);
    __nv_bfloat16 l0 = __float2bfloat16_rn(v.x - __bfloat162float(h0));
    __nv_bfloat16 l1 = __float2bfloat16_rn(v.y - __bfloat162float(h1));
    __nv_bfloat16 l2 = __float2bfloat16_rn(v.z - __bfloat162float(h2));
    __nv_bfloat16 l3 = __float2bfloat16_rn(v.w - __bfloat162float(h3));
    ((uint2*)hi)[i] = make_uint2(pk(h0, h1), pk(h2, h3));
    ((uint2*)lo)[i] = make_uint2(pk(l0, l1), pk(l2, l3));
}

// ---------------- tensor-core GEMM (pre-split bf16x3) ----------------
__device__ __forceinline__ void ldsm_x4(unsigned* r, const void* p) {
    unsigned a = (unsigned)__cvta_generic_to_shared(p);
    asm volatile("ldmatrix.sync.aligned.m8n8.x4.shared.b16 {%0,%1,%2,%3}, [%4];"
                 : "=r"(r[0]), "=r"(r[1]), "=r"(r[2]), "=r"(r[3]) : "r"(a));
}

__device__ __forceinline__ void ldsm_x4_t(unsigned* r, const void* p) {
    unsigned a = (unsigned)__cvta_generic_to_shared(p);
    asm volatile("ldmatrix.sync.aligned.m8n8.x4.trans.shared.b16 {%0,%1,%2,%3}, [%4];"
                 : "=r"(r[0]), "=r"(r[1]), "=r"(r[2]), "=r"(r[3]) : "r"(a));
}

__device__ __forceinline__ void mma_bf16(float* d, const unsigned* a, const unsigned* b) {
    asm volatile(
        "mma.sync.aligned.m16n8k16.row.col.f32.bf16.bf16.f32 "
        "{%0,%1,%2,%3}, {%4,%5,%6,%7}, {%8,%9}, {%0,%1,%2,%3};"
        : "+f"(d[0]), "+f"(d[1]), "+f"(d[2]), "+f"(d[3])
        : "r"(a[0]), "r"(a[1]), "r"(a[2]), "r"(a[3]), "r"(b[0]), "r"(b[1]));
}

// C[M,N] = (Ah+Al)[M,K] @ (Bh+Bl)[K,N]  (3-term), writes H only.
__global__ __launch_bounds__(256, 1) void gemm_bf16x3(
    int M, int N, int K,
    const __nv_bfloat16* __restrict__ AH, const __nv_bfloat16* __restrict__ AL,
    const __nv_bfloat16* __restrict__ BH, const __nv_bfloat16* __restrict__ BL,
    float* __restrict__ H)
{
    const int ASTR = 40;    // 32 + 8 pad
    const int BSTR = 136;   // 128 + 8 pad
    __shared__ unsigned short Ah[128 * ASTR], Al[128 * ASTR];
    __shared__ unsigned short Bh[32 * BSTR],  Bl[32 * BSTR];

    const int tid = threadIdx.x, lane = tid & 31, warp = tid >> 5;
    const int wm = warp >> 2, wn = warp & 3;
    const int bRow = blockIdx.x, bCol = blockIdx.y;

    // A tile 128x32 bf16: thread loads 8 elems in 2 rows per array
    const int arow0 = tid >> 2;          // 0..63
    const int acol0 = (tid & 3) * 8;     // 0,8,16,24
    // B tile 32x128 bf16
    const int brow0 = tid >> 4;          // 0..15
    const int bcol0 = (tid & 15) * 8;    // 0..120

    uint4 aH[2], aL[2], bH[2], bL[2];
    const int nk = K / 32;

    auto LDG = [&](int kb) {
#pragma unroll
        for (int i = 0; i < 2; i++) {
            int gr = bRow * 128 + arow0 + 64 * i;
            if (gr < M) {
                size_t off = (size_t)gr * K + kb * 32 + acol0;
                aH[i] = *(const uint4*)(AH + off);
                aL[i] = *(const uint4*)(AL + off);
            } else {
                aH[i] = make_uint4(0, 0, 0, 0);
                aL[i] = make_uint4(0, 0, 0, 0);
            }
        }
#pragma unroll
        for (int i = 0; i < 2; i++) {
            int gk = kb * 32 + brow0 + 16 * i;
            size_t off = (size_t)gk * N + bCol * 128 + bcol0;
            bH[i] = *(const uint4*)(BH + off);
            bL[i] = *(const uint4*)(BL + off);
        }
    };

    float acc[4][4][4];
#pragma unroll
    for (int mi = 0; mi < 4; mi++)
#pragma unroll
        for (int nj = 0; nj < 4; nj++)
#pragma unroll
            for (int r = 0; r < 4; r++) acc[mi][nj][r] = 0.f;

    LDG(0);

    const int g8  = lane & 7;
    const int m01 = (lane >> 3) & 1;
    const int m23 = lane >> 4;

    for (int kb = 0; kb < nk; kb++) {
        __syncthreads();
#pragma unroll
        for (int i = 0; i < 2; i++) {
            int row = arow0 + 64 * i;
            *(uint4*)&Ah[row * ASTR + acol0] = aH[i];
            *(uint4*)&Al[row * ASTR + acol0] = aL[i];
        }
#pragma unroll
        for (int i = 0; i < 2; i++) {
            int krow = brow0 + 16 * i;
            *(uint4*)&Bh[krow * BSTR + bcol0] = bH[i];
            *(uint4*)&Bl[krow * BSTR + bcol0] = bL[i];
        }
        __syncthreads();

        if (kb + 1 < nk) LDG(kb + 1);

#pragma unroll
        for (int kk = 0; kk < 2; kk++) {
            const int k0 = kk * 16;
            unsigned aFh[4][4], aFl[4][4], bFh[4][2], bFl[4][2];
#pragma unroll
            for (int mi = 0; mi < 4; mi++) {
                int row = wm * 64 + mi * 16 + g8 + m01 * 8;
                int kof = k0 + m23 * 8;
                ldsm_x4(aFh[mi], &Ah[row * ASTR + kof]);
                ldsm_x4(aFl[mi], &Al[row * ASTR + kof]);
            }
#pragma unroll
            for (int bj = 0; bj < 2; bj++) {
                int krow = k0 + g8 + m01 * 8;
                int ncol = wn * 32 + bj * 16 + m23 * 8;
                unsigned t[4];
                ldsm_x4_t(t, &Bh[krow * BSTR + ncol]);
                bFh[2 * bj][0] = t[0]; bFh[2 * bj][1] = t[1];
                bFh[2 * bj + 1][0] = t[2]; bFh[2 * bj + 1][1] = t[3];
                ldsm_x4_t(t, &Bl[krow * BSTR + ncol]);
                bFl[2 * bj][0] = t[0]; bFl[2 * bj][1] = t[1];
                bFl[2 * bj + 1][0] = t[2]; bFl[2 * bj + 1][1] = t[3];
            }
#pragma unroll
            for (int mi = 0; mi < 4; mi++)
#pragma unroll
                for (int nj = 0; nj < 4; nj++) {
                    mma_bf16(acc[mi][nj], aFh[mi], bFh[nj]);
                    mma_bf16(acc[mi][nj], aFh[mi], bFl[nj]);
                    mma_bf16(acc[mi][nj], aFl[mi], bFh[nj]);
                }
        }
    }

    const int gg = lane >> 2, cc = lane & 3;
#pragma unroll
    for (int mi = 0; mi < 4; mi++) {
        int rb = bRow * 128 + wm * 64 + mi * 16;
        int r0 = rb + gg, r1 = rb + gg + 8;
#pragma unroll
        for (int nj = 0; nj < 4; nj++) {
            int col = bCol * 128 + wn * 32 + nj * 8 + 2 * cc;
            float* a = acc[mi][nj];
            if (r0 < M) *(float2*)(H + (size_t)r0 * N + col) = make_float2(a[0], a[1]);
            if (r1 < M) *(float2*)(H + (size_t)r1 * N + col) = make_float2(a[2], a[3]);
        }
    }
}

// ---------------- CSR gather aggregation (atomic-free) ----------------
// one warp per dst: agg[dst] = bias + dinv[dst]^2*h[dst] + sum_e nw_e * h[src_e]
__global__ __launch_bounds__(256) void gather_agg(
    const float* __restrict__ h, const float* __restrict__ bias,
    float* __restrict__ agg, int M)
{
    int warp = (blockIdx.x * blockDim.x + threadIdx.x) >> 5;
    int lane = threadIdx.x & 31;
    if (warp >= M) return;
    int dst = warp;
    int beg = g_offsets[dst], end = g_offsets[dst + 1];

    float4 a0 = make_float4(0.f, 0.f, 0.f, 0.f);
    float4 a1 = make_float4(0.f, 0.f, 0.f, 0.f);
    for (int e = beg; e < end; e++) {
        uint2 p = g_epack[e];
        float nw = __uint_as_float(p.y);
        const float4* hs = (const float4*)(h + (size_t)p.x * F);
        float4 v0 = hs[lane], v1 = hs[lane + 32];
        a0.x += nw * v0.x; a0.y += nw * v0.y; a0.z += nw * v0.z; a0.w += nw * v0.w;
        a1.x += nw * v1.x; a1.y += nw * v1.y; a1.z += nw * v1.z; a1.w += nw * v1.w;
    }
    float di = g_dinv[dst], s = di * di;
    const float4* hd = (const float4*)(h + (size_t)dst * F);
    const float4* bp = (const float4*)bias;
    float4 u0 = hd[lane], u1 = hd[lane + 32];
    float4 b0 = bp[lane], b1 = bp[lane + 32];
    float4 o0 = make_float4(b0.x + s * u0.x + a0.x, b0.y + s * u0.y + a0.y,
                            b0.z + s * u0.z + a0.z, b0.w + s * u0.w + a0.w);
    float4 o1 = make_float4(b1.x + s * u1.x + a1.x, b1.y + s * u1.y + a1.y,
                            b1.z + s * u1.z + a1.z, b1.w + s * u1.w + a1.w);
    float4* ap = (float4*)(agg + (size_t)dst * F);
    ap[lane] = o0;
    ap[lane + 32] = o1;
}

// ---------------- batchnorm stats over relu(agg2) ----------------
__global__ void bn_zero() {
    int f = threadIdx.x;
    g_bnsum[f] = 0.0f;
    g_bnssq[f] = 0.0f;
}

__global__ void bn_stats(const float* __restrict__ agg2, int M, int rows_per_block) {
    int f = threadIdx.x;
    long r0 = blockIdx.x * (long)rows_per_block;
    long r1 = r0 + rows_per_block; if (r1 > M) r1 = M;
    float s = 0.f, ss = 0.f;
    for (long r = r0; r < r1; r++) {
        float v = fmaxf(agg2[r * F + f], 0.f);
        s += v; ss += v * v;
    }
    atomicAdd(&g_bnsum[f], s);
    atomicAdd(&g_bnssq[f], ss);
}

// ---------------- fused relu + BN + LN epilogue ----------------
__global__ void bn_ln_final(const float* __restrict__ agg2,
                            const float* __restrict__ bg, const float* __restrict__ bb,
                            const float* __restrict__ lg, const float* __restrict__ lb,
                            float* __restrict__ out, int M) {
    long r = blockIdx.x;
    int  f = threadIdx.x;
    int  lane = f & 31, wid = f >> 5;
    float invM = 1.0f / (float)M;

    float mu  = g_bnsum[f] * invM;
    float var = g_bnssq[f] * invM - mu * mu;
    float v = fmaxf(agg2[r * F + f], 0.f);
    float y = (v - mu) * rsqrtf(var + EPSV) * bg[f] + bb[f];

    float s = y, ss = y * y;
#pragma unroll
    for (int o = 16; o > 0; o >>= 1) {
        s  += __shfl_xor_sync(0xffffffffu, s,  o);
        ss += __shfl_xor_sync(0xffffffffu, ss, o);
    }
    __shared__ float reds[8], redss[8];
    if (lane == 0) { reds[wid] = s; redss[wid] = ss; }
    __syncthreads();
    if (wid == 0) {
        float a = lane < 8 ? reds[lane]  : 0.f;
        float b = lane < 8 ? redss[lane] : 0.f;
#pragma unroll
        for (int o = 4; o > 0; o >>= 1) {
            a += __shfl_xor_sync(0xffffffffu, a, o);
            b += __shfl_xor_sync(0xffffffffu, b, o);
        }
        if (lane == 0) { reds[0] = a; redss[0] = b; }
    }
    __syncthreads();
    float lmu  = reds[0]  * (1.0f / F);
    float lvar = redss[0] * (1.0f / F) - lmu * lmu;
    out[r * F + f] = (y - lmu) * rsqrtf(lvar + EPSV) * lg[f] + lb[f];
}

// ---------------- launcher ----------------
extern "C" void kernel_launch(void* const* d_in, const int* in_sizes, int n_in,
                              void* d_out, int out_size) {
    const float* x  = (const float*)d_in[0];
    const void*  ei = d_in[1];
    const float* ew = (const float*)d_in[2];
    const float* W1 = (const float*)d_in[3];
    const float* b1 = (const float*)d_in[4];
    const float* W2 = (const float*)d_in[5];
    const float* b2 = (const float*)d_in[6];
    const float* bg = (const float*)d_in[7];
    const float* bb = (const float*)d_in[8];
    const float* lg = (const float*)d_in[9];
    const float* lb = (const float*)d_in[10];
    float* out = (float*)d_out;

    int  n = in_sizes[0] / NFEAT;            // 50000
    long E = in_sizes[1] / 2;                // 800000
    if (E > E_MAX) E = E_MAX;

    float* h1;   cudaGetSymbolAddress((void**)&h1,   g_h1);
    float* agg1; cudaGetSymbolAddress((void**)&agg1, g_agg1);
    float* h2;   cudaGetSymbolAddress((void**)&h2,   g_h2);
    float* agg2; cudaGetSymbolAddress((void**)&agg2, g_agg2);
    __nv_bfloat16 *xh, *xl, *a1h, *a1l, *w1h, *w1l, *w2h, *w2l;
    cudaGetSymbolAddress((void**)&xh,  g_xh);
    cudaGetSymbolAddress((void**)&xl,  g_xl);
    cudaGetSymbolAddress((void**)&a1h, g_a1h);
    cudaGetSymbolAddress((void**)&a1l, g_a1l);
    cudaGetSymbolAddress((void**)&w1h, g_w1h);
    cudaGetSymbolAddress((void**)&w1l, g_w1l);
    cudaGetSymbolAddress((void**)&w2h, g_w2h);
    cudaGetSymbolAddress((void**)&w2l, g_w2l);

    int eb = (int)((E + 255) / 256);

    // 0) dtype detection
    detect_idx_dtype<<<1, 256>>>((const int*)ei, 1024);

    // 1) degree + CSR build
    zero_counts_deg<<<(n + 255) / 256, 256>>>(n);
    histo_deg<<<eb, 256>>>(ei, ew, E);
    compute_dinv<<<(n + 255) / 256, 256>>>(n);
    scan_offsets<<<1, 1024>>>(n);
    scatter_edges<<<eb, 256>>>(ei, ew, E);

    // 2) pre-convert inputs to bf16 hi/lo
    long x4  = (long)n * NFEAT / 4;
    long w14 = (long)NFEAT * F / 4;
    long w24 = (long)F * F / 4;
    long a4  = (long)n * F / 4;
    convert_split<<<(int)((x4 + 255) / 256), 256>>>(x,  xh,  xl,  x4,  0);
    convert_split<<<(int)((w14 + 255) / 256), 256>>>(W1, w1h, w1l, w14, 0);
    convert_split<<<(int)((w24 + 255) / 256), 256>>>(W2, w2h, w2l, w24, 0);

    dim3 gg((n + 127) / 128, F / 128);
    int gatherBlocks = (n * 32 + 255) / 256;

    // 3) layer 1
    gemm_bf16x3<<<gg, 256>>>(n, F, NFEAT, xh, xl, w1h, w1l, h1);
    gather_agg<<<gatherBlocks, 256>>>(h1, b1, agg1, n);

    // 4) layer 2 (relu fused into conversion)
    convert_split<<<(int)((a4 + 255) / 256), 256>>>(agg1, a1h, a1l, a4, 1);
    gemm_bf16x3<<<gg, 256>>>(n, F, F, a1h, a1l, w2h, w2l, h2);
    gather_agg<<<gatherBlocks, 256>>>(h2, b2, agg2, n);

    // 5) BN stats + fused BN/LN
    bn_zero<<<1, F>>>();
    const int RPB = 128;
    bn_stats<<<(n + RPB - 1) / RPB, F>>>(agg2, n, RPB);
    bn_ln_final<<<n, F>>>(agg2, bg, bb, lg, lb, out, n);
}

// round 7
// speedup vs baseline: 1.9885x; 1.0064x over previous
#include <cuda_runtime.h>
#include <cuda_bf16.h>
#include <stdint.h>

#define N_NODES 50000
#define F 256
#define NFEAT 1024
#define E_MAX 800000
#define EPSV 1e-5f
typedef __nv_bfloat16 BF16;

// ---------------- scratch (__device__ globals) ----------------
__device__ float g_h1  [(size_t)N_NODES * F];
__device__ float g_h2  [(size_t)N_NODES * F];
__device__ float g_agg2[(size_t)N_NODES * F];
__device__ BF16 g_xh[(size_t)N_NODES * NFEAT];
__device__ BF16 g_xl[(size_t)N_NODES * NFEAT];
__device__ BF16 g_a1h[(size_t)N_NODES * F];
__device__ BF16 g_a1l[(size_t)N_NODES * F];
__device__ BF16 g_w1h[NFEAT * F], g_w1l[NFEAT * F];
__device__ BF16 g_w2h[F * F],     g_w2l[F * F];
__device__ float g_deg [N_NODES];
__device__ float g_dinv[N_NODES];
__device__ int   g_counts [N_NODES];
__device__ int   g_offsets[N_NODES + 1];
__device__ int   g_cursor [N_NODES];
__device__ uint2 g_epack  [E_MAX];          // (src, norm-weight)
__device__ float g_bnsum[F];
__device__ float g_bnssq[F];
__device__ int   g_is64;

// ---------------- edge_index dtype detection ----------------
__global__ void detect_idx_dtype(const int* ei32, int n_check) {
    __shared__ int bad;
    if (threadIdx.x == 0) bad = 0;
    __syncthreads();
    for (int i = threadIdx.x; i < n_check; i += blockDim.x)
        if (ei32[2 * i + 1] != 0) bad = 1;
    __syncthreads();
    if (threadIdx.x == 0) g_is64 = bad ? 0 : 1;
}

__device__ __forceinline__ long ld_idx(const void* ei, long i) {
    return g_is64 ? (long)((const long long*)ei)[i] : (long)((const int*)ei)[i];
}

// ---------------- degree + CSR ----------------
__global__ void zero_counts_deg(int n) {
    int i = blockIdx.x * blockDim.x + threadIdx.x;
    if (i < n) { g_counts[i] = 0; g_deg[i] = 1.0f; }
}

__global__ void histo_deg(const void* ei, const float* w, long E) {
    long e = blockIdx.x * (long)blockDim.x + threadIdx.x;
    if (e >= E) return;
    long dst = ld_idx(ei, E + e);
    atomicAdd(&g_deg[dst], w[e]);
    atomicAdd(&g_counts[(int)dst], 1);
}

__global__ void compute_dinv(int n) {
    int i = blockIdx.x * blockDim.x + threadIdx.x;
    if (i < n) {
        float d = g_deg[i];
        g_dinv[i] = d > 0.0f ? rsqrtf(fmaxf(d, 1e-30f)) : 0.0f;
    }
}

__global__ __launch_bounds__(1024) void scan_offsets(int n) {
    __shared__ int ssum[1024];
    int t = threadIdx.x;
    int chunk = (n + 1023) / 1024;
    int beg = t * chunk, end = min(beg + chunk, n);
    int s = 0;
    for (int i = beg; i < end; i++) s += g_counts[i];
    ssum[t] = s;
    __syncthreads();
    for (int o = 1; o < 1024; o <<= 1) {
        int u = (t >= o) ? ssum[t - o] : 0;
        __syncthreads();
        ssum[t] += u;
        __syncthreads();
    }
    int run = ssum[t] - s;
    for (int i = beg; i < end; i++) {
        g_offsets[i] = run;
        g_cursor[i]  = run;
        run += g_counts[i];
    }
    if (t == 1023) g_offsets[n] = run;
}

__global__ void scatter_edges(const void* ei, const float* w, long E) {
    long e = blockIdx.x * (long)blockDim.x + threadIdx.x;
    if (e >= E) return;
    long src = ld_idx(ei, e);
    long dst = ld_idx(ei, E + e);
    float nw = g_dinv[src] * w[e] * g_dinv[dst];
    int pos = atomicAdd(&g_cursor[(int)dst], 1);
    g_epack[pos] = make_uint2((unsigned)src, __float_as_uint(nw));
}

// ---------------- fp32 -> bf16 hi/lo split ----------------
__device__ __forceinline__ unsigned pk(BF16 lo, BF16 hi) {
    __nv_bfloat162 t = __halves2bfloat162(lo, hi);
    return *reinterpret_cast<unsigned*>(&t);
}

__global__ void convert_split(const float* __restrict__ in,
                              BF16* __restrict__ hi, BF16* __restrict__ lo,
                              long n4) {
    long i = blockIdx.x * (long)blockDim.x + threadIdx.x;
    if (i >= n4) return;
    float4 v = ((const float4*)in)[i];
    BF16 h0 = __float2bfloat16_rn(v.x), h1 = __float2bfloat16_rn(v.y);
    BF16 h2 = __float2bfloat16_rn(v.z), h3 = __float2bfloat16_rn(v.w);
    BF16 l0 = __float2bfloat16_rn(v.x - __bfloat162float(h0));
    BF16 l1 = __float2bfloat16_rn(v.y - __bfloat162float(h1));
    BF16 l2 = __float2bfloat16_rn(v.z - __bfloat162float(h2));
    BF16 l3 = __float2bfloat16_rn(v.w - __bfloat162float(h3));
    ((uint2*)hi)[i] = make_uint2(pk(h0, h1), pk(h2, h3));
    ((uint2*)lo)[i] = make_uint2(pk(l0, l1), pk(l2, l3));
}

// ---------------- transpose + split (kept for completeness, not used for B here) ----
// (weights stay [K][N] row-major; GEMM loads them K-major like round 3)

// ---------------- tensor-core GEMM (pre-split bf16x3, mma.sync) ----------------
__device__ __forceinline__ void ldsm_x4(unsigned* r, const void* p) {
    unsigned a = (unsigned)__cvta_generic_to_shared(p);
    asm volatile("ldmatrix.sync.aligned.m8n8.x4.shared.b16 {%0,%1,%2,%3}, [%4];"
                 : "=r"(r[0]), "=r"(r[1]), "=r"(r[2]), "=r"(r[3]) : "r"(a));
}

__device__ __forceinline__ void ldsm_x4_t(unsigned* r, const void* p) {
    unsigned a = (unsigned)__cvta_generic_to_shared(p);
    asm volatile("ldmatrix.sync.aligned.m8n8.x4.trans.shared.b16 {%0,%1,%2,%3}, [%4];"
                 : "=r"(r[0]), "=r"(r[1]), "=r"(r[2]), "=r"(r[3]) : "r"(a));
}

__device__ __forceinline__ void mma_bf16(float* d, const unsigned* a, const unsigned* b) {
    asm volatile(
        "mma.sync.aligned.m16n8k16.row.col.f32.bf16.bf16.f32 "
        "{%0,%1,%2,%3}, {%4,%5,%6,%7}, {%8,%9}, {%0,%1,%2,%3};"
        : "+f"(d[0]), "+f"(d[1]), "+f"(d[2]), "+f"(d[3])
        : "r"(a[0]), "r"(a[1]), "r"(a[2]), "r"(a[3]), "r"(b[0]), "r"(b[1]));
}

// C[M,N] = (Ah+Al)[M,K] @ (Bh+Bl)[K,N]  (3-term), writes H.
__global__ __launch_bounds__(256, 1) void gemm_bf16x3(
    int M, int N, int K,
    const BF16* __restrict__ AH, const BF16* __restrict__ AL,
    const BF16* __restrict__ BH, const BF16* __restrict__ BL,
    float* __restrict__ H)
{
    const int ASTR = 40;    // 32 + 8 pad
    const int BSTR = 136;   // 128 + 8 pad
    __shared__ unsigned short Ah[128 * ASTR], Al[128 * ASTR];
    __shared__ unsigned short Bh[32 * BSTR],  Bl[32 * BSTR];

    const int tid = threadIdx.x, lane = tid & 31, warp = tid >> 5;
    const int wm = warp >> 2, wn = warp & 3;
    const int bRow = blockIdx.x, bCol = blockIdx.y;

    const int arow0 = tid >> 2;          // 0..63
    const int acol0 = (tid & 3) * 8;     // 0,8,16,24
    const int brow0 = tid >> 4;          // 0..15
    const int bcol0 = (tid & 15) * 8;    // 0..120

    uint4 aH[2], aL[2], bH[2], bL[2];
    const int nk = K / 32;

    auto LDG = [&](int kb) {
#pragma unroll
        for (int i = 0; i < 2; i++) {
            int gr = bRow * 128 + arow0 + 64 * i;
            if (gr < M) {
                size_t off = (size_t)gr * K + kb * 32 + acol0;
                aH[i] = *(const uint4*)(AH + off);
                aL[i] = *(const uint4*)(AL + off);
            } else {
                aH[i] = make_uint4(0, 0, 0, 0);
                aL[i] = make_uint4(0, 0, 0, 0);
            }
        }
#pragma unroll
        for (int i = 0; i < 2; i++) {
            int gk = kb * 32 + brow0 + 16 * i;
            size_t off = (size_t)gk * N + bCol * 128 + bcol0;
            bH[i] = *(const uint4*)(BH + off);
            bL[i] = *(const uint4*)(BL + off);
        }
    };

    float acc[4][4][4];
#pragma unroll
    for (int mi = 0; mi < 4; mi++)
#pragma unroll
        for (int nj = 0; nj < 4; nj++)
#pragma unroll
            for (int r = 0; r < 4; r++) acc[mi][nj][r] = 0.f;

    LDG(0);

    const int g8  = lane & 7;
    const int m01 = (lane >> 3) & 1;
    const int m23 = lane >> 4;

    for (int kb = 0; kb < nk; kb++) {
        __syncthreads();
#pragma unroll
        for (int i = 0; i < 2; i++) {
            int row = arow0 + 64 * i;
            *(uint4*)&Ah[row * ASTR + acol0] = aH[i];
            *(uint4*)&Al[row * ASTR + acol0] = aL[i];
        }
#pragma unroll
        for (int i = 0; i < 2; i++) {
            int krow = brow0 + 16 * i;
            *(uint4*)&Bh[krow * BSTR + bcol0] = bH[i];
            *(uint4*)&Bl[krow * BSTR + bcol0] = bL[i];
        }
        __syncthreads();

        if (kb + 1 < nk) LDG(kb + 1);

#pragma unroll
        for (int kk = 0; kk < 2; kk++) {
            const int k0 = kk * 16;
            unsigned aFh[4][4], aFl[4][4], bFh[4][2], bFl[4][2];
#pragma unroll
            for (int mi = 0; mi < 4; mi++) {
                int row = wm * 64 + mi * 16 + g8 + m01 * 8;
                int kof = k0 + m23 * 8;
                ldsm_x4(aFh[mi], &Ah[row * ASTR + kof]);
                ldsm_x4(aFl[mi], &Al[row * ASTR + kof]);
            }
#pragma unroll
            for (int bj = 0; bj < 2; bj++) {
                int krow = k0 + g8 + m01 * 8;
                int ncol = wn * 32 + bj * 16 + m23 * 8;
                unsigned t[4];
                ldsm_x4_t(t, &Bh[krow * BSTR + ncol]);
                bFh[2 * bj][0] = t[0]; bFh[2 * bj][1] = t[1];
                bFh[2 * bj + 1][0] = t[2]; bFh[2 * bj + 1][1] = t[3];
                ldsm_x4_t(t, &Bl[krow * BSTR + ncol]);
                bFl[2 * bj][0] = t[0]; bFl[2 * bj][1] = t[1];
                bFl[2 * bj + 1][0] = t[2]; bFl[2 * bj + 1][1] = t[3];
            }
#pragma unroll
            for (int mi = 0; mi < 4; mi++)
#pragma unroll
                for (int nj = 0; nj < 4; nj++) {
                    mma_bf16(acc[mi][nj], aFh[mi], bFh[nj]);
                    mma_bf16(acc[mi][nj], aFh[mi], bFl[nj]);
                    mma_bf16(acc[mi][nj], aFl[mi], bFh[nj]);
                }
        }
    }

    const int gg = lane >> 2, cc = lane & 3;
#pragma unroll
    for (int mi = 0; mi < 4; mi++) {
        int rb = bRow * 128 + wm * 64 + mi * 16;
        int r0 = rb + gg, r1 = rb + gg + 8;
#pragma unroll
        for (int nj = 0; nj < 4; nj++) {
            int col = bCol * 128 + wn * 32 + nj * 8 + 2 * cc;
            float* a = acc[mi][nj];
            if (r0 < M) *(float2*)(H + (size_t)r0 * N + col) = make_float2(a[0], a[1]);
            if (r1 < M) *(float2*)(H + (size_t)r1 * N + col) = make_float2(a[2], a[3]);
        }
    }
}

// ---------------- CSR gather aggregation (atomic-free, 2-edge unrolled) ----------------
// agg[dst] = relu( bias + dinv[dst]^2*h[dst] + sum_e nw_e*h[src_e] )
// MODE 0: write fp32 row to AGGF.   MODE 1: write bf16 hi/lo split to AH/AL.
template <int MODE>
__global__ __launch_bounds__(256) void gather_agg(
    const float* __restrict__ h, const float* __restrict__ bias,
    float* __restrict__ AGGF, BF16* __restrict__ AHo, BF16* __restrict__ ALo,
    int M)
{
    int warp = (blockIdx.x * blockDim.x + threadIdx.x) >> 5;
    int lane = threadIdx.x & 31;
    if (warp >= M) return;
    int dst = warp;
    int beg = g_offsets[dst], end = g_offsets[dst + 1];

    float4 s0a = make_float4(0.f, 0.f, 0.f, 0.f);
    float4 s0b = make_float4(0.f, 0.f, 0.f, 0.f);
    float4 s1a = make_float4(0.f, 0.f, 0.f, 0.f);
    float4 s1b = make_float4(0.f, 0.f, 0.f, 0.f);

    int e = beg;
    for (; e + 2 <= end; e += 2) {
        uint2 p0 = g_epack[e];
        uint2 p1 = g_epack[e + 1];
        float w0 = __uint_as_float(p0.y);
        float w1 = __uint_as_float(p1.y);
        const float4* q0 = (const float4*)(h + (size_t)p0.x * F);
        const float4* q1 = (const float4*)(h + (size_t)p1.x * F);
        float4 u00 = q0[lane], u01 = q0[lane + 32];
        float4 u10 = q1[lane], u11 = q1[lane + 32];
        s0a.x += w0 * u00.x; s0a.y += w0 * u00.y; s0a.z += w0 * u00.z; s0a.w += w0 * u00.w;
        s0b.x += w0 * u01.x; s0b.y += w0 * u01.y; s0b.z += w0 * u01.z; s0b.w += w0 * u01.w;
        s1a.x += w1 * u10.x; s1a.y += w1 * u10.y; s1a.z += w1 * u10.z; s1a.w += w1 * u10.w;
        s1b.x += w1 * u11.x; s1b.y += w1 * u11.y; s1b.z += w1 * u11.z; s1b.w += w1 * u11.w;
    }
    if (e < end) {
        uint2 p0 = g_epack[e];
        float w0 = __uint_as_float(p0.y);
        const float4* q0 = (const float4*)(h + (size_t)p0.x * F);
        float4 u00 = q0[lane], u01 = q0[lane + 32];
        s0a.x += w0 * u00.x; s0a.y += w0 * u00.y; s0a.z += w0 * u00.z; s0a.w += w0 * u00.w;
        s0b.x += w0 * u01.x; s0b.y += w0 * u01.y; s0b.z += w0 * u01.z; s0b.w += w0 * u01.w;
    }

    float di = g_dinv[dst], s = di * di;
    const float4* hd = (const float4*)(h + (size_t)dst * F);
    const float4* bp = (const float4*)bias;
    float4 u0 = hd[lane], u1 = hd[lane + 32];
    float4 b0 = bp[lane], b1 = bp[lane + 32];
    float4 o0, o1;
    o0.x = fmaxf(b0.x + s * u0.x + s0a.x + s1a.x, 0.f);
    o0.y = fmaxf(b0.y + s * u0.y + s0a.y + s1a.y, 0.f);
    o0.z = fmaxf(b0.z + s * u0.z + s0a.z + s1a.z, 0.f);
    o0.w = fmaxf(b0.w + s * u0.w + s0a.w + s1a.w, 0.f);
    o1.x = fmaxf(b1.x + s * u1.x + s0b.x + s1b.x, 0.f);
    o1.y = fmaxf(b1.y + s * u1.y + s0b.y + s1b.y, 0.f);
    o1.z = fmaxf(b1.z + s * u1.z + s0b.z + s1b.z, 0.f);
    o1.w = fmaxf(b1.w + s * u1.w + s0b.w + s1b.w, 0.f);

    if (MODE == 0) {
        float4* ap = (float4*)(AGGF + (size_t)dst * F);
        ap[lane] = o0;
        ap[lane + 32] = o1;
    } else {
        // split to bf16 hi/lo, write 4 bf16 (uint2) per half-row chunk
        BF16 h0 = __float2bfloat16_rn(o0.x), h1 = __float2bfloat16_rn(o0.y);
        BF16 h2 = __float2bfloat16_rn(o0.z), h3 = __float2bfloat16_rn(o0.w);
        BF16 l0 = __float2bfloat16_rn(o0.x - __bfloat162float(h0));
        BF16 l1 = __float2bfloat16_rn(o0.y - __bfloat162float(h1));
        BF16 l2 = __float2bfloat16_rn(o0.z - __bfloat162float(h2));
        BF16 l3 = __float2bfloat16_rn(o0.w - __bfloat162float(h3));
        BF16 h4 = __float2bfloat16_rn(o1.x), h5 = __float2bfloat16_rn(o1.y);
        BF16 h6 = __float2bfloat16_rn(o1.z), h7 = __float2bfloat16_rn(o1.w);
        BF16 l4 = __float2bfloat16_rn(o1.x - __bfloat162float(h4));
        BF16 l5 = __float2bfloat16_rn(o1.y - __bfloat162float(h5));
        BF16 l6 = __float2bfloat16_rn(o1.z - __bfloat162float(h6));
        BF16 l7 = __float2bfloat16_rn(o1.w - __bfloat162float(h7));
        uint2* ph = (uint2*)(AHo + (size_t)dst * F);
        uint2* pl = (uint2*)(ALo + (size_t)dst * F);
        ph[lane]      = make_uint2(pk(h0, h1), pk(h2, h3));
        ph[lane + 32] = make_uint2(pk(h4, h5), pk(h6, h7));
        pl[lane]      = make_uint2(pk(l0, l1), pk(l2, l3));
        pl[lane + 32] = make_uint2(pk(l4, l5), pk(l6, l7));
    }
}

// ---------------- BN stats over agg2 (already relu'd) ----------------
__global__ void bn_zero() {
    int f = threadIdx.x;
    g_bnsum[f] = 0.0f;
    g_bnssq[f] = 0.0f;
}

__global__ void bn_stats(const float* __restrict__ agg2, int M, int rows_per_block) {
    int f = threadIdx.x;
    long r0 = blockIdx.x * (long)rows_per_block;
    long r1 = r0 + rows_per_block; if (r1 > M) r1 = M;
    float s = 0.f, ss = 0.f;
    for (long r = r0; r < r1; r++) {
        float v = agg2[r * F + f];
        s += v; ss += v * v;
    }
    atomicAdd(&g_bnsum[f], s);
    atomicAdd(&g_bnssq[f], ss);
}

// ---------------- fused BN + LN (agg2 already relu'd) ----------------
__global__ void bn_ln_final(const float* __restrict__ agg2,
                            const float* __restrict__ bg, const float* __restrict__ bb,
                            const float* __restrict__ lg, const float* __restrict__ lb,
                            float* __restrict__ out, int M) {
    long r = blockIdx.x;
    int  f = threadIdx.x;
    int  lane = f & 31, wid = f >> 5;
    float invM = 1.0f / (float)M;

    float mu  = g_bnsum[f] * invM;
    float var = g_bnssq[f] * invM - mu * mu;
    float v = agg2[r * F + f];
    float y = (v - mu) * rsqrtf(var + EPSV) * bg[f] + bb[f];

    float s = y, ss = y * y;
#pragma unroll
    for (int o = 16; o > 0; o >>= 1) {
        s  += __shfl_xor_sync(0xffffffffu, s,  o);
        ss += __shfl_xor_sync(0xffffffffu, ss, o);
    }
    __shared__ float reds[8], redss[8];
    if (lane == 0) { reds[wid] = s; redss[wid] = ss; }
    __syncthreads();
    if (wid == 0) {
        float a = lane < 8 ? reds[lane]  : 0.f;
        float b = lane < 8 ? redss[lane] : 0.f;
#pragma unroll
        for (int o = 4; o > 0; o >>= 1) {
            a += __shfl_xor_sync(0xffffffffu, a, o);
            b += __shfl_xor_sync(0xffffffffu, b, o);
        }
        if (lane == 0) { reds[0] = a; redss[0] = b; }
    }
    __syncthreads();
    float lmu  = reds[0]  * (1.0f / F);
    float lvar = redss[0] * (1.0f / F) - lmu * lmu;
    out[r * F + f] = (y - lmu) * rsqrtf(lvar + EPSV) * lg[f] + lb[f];
}

// ---------------- launcher ----------------
extern "C" void kernel_launch(void* const* d_in, const int* in_sizes, int n_in,
                              void* d_out, int out_size) {
    const float* x  = (const float*)d_in[0];
    const void*  ei = d_in[1];
    const float* ew = (const float*)d_in[2];
    const float* W1 = (const float*)d_in[3];
    const float* b1 = (const float*)d_in[4];
    const float* W2 = (const float*)d_in[5];
    const float* b2 = (const float*)d_in[6];
    const float* bg = (const float*)d_in[7];
    const float* bb = (const float*)d_in[8];
    const float* lg = (const float*)d_in[9];
    const float* lb = (const float*)d_in[10];
    float* out = (float*)d_out;

    int  n = in_sizes[0] / NFEAT;            // 50000
    long E = in_sizes[1] / 2;                // 800000
    if (E > E_MAX) E = E_MAX;

    float* h1;   cudaGetSymbolAddress((void**)&h1,   g_h1);
    float* h2;   cudaGetSymbolAddress((void**)&h2,   g_h2);
    float* agg2; cudaGetSymbolAddress((void**)&agg2, g_agg2);
    BF16 *xh, *xl, *a1h, *a1l, *w1h, *w1l, *w2h, *w2l;
    cudaGetSymbolAddress((void**)&xh,  g_xh);
    cudaGetSymbolAddress((void**)&xl,  g_xl);
    cudaGetSymbolAddress((void**)&a1h, g_a1h);
    cudaGetSymbolAddress((void**)&a1l, g_a1l);
    cudaGetSymbolAddress((void**)&w1h, g_w1h);
    cudaGetSymbolAddress((void**)&w1l, g_w1l);
    cudaGetSymbolAddress((void**)&w2h, g_w2h);
    cudaGetSymbolAddress((void**)&w2l, g_w2l);

    int eb = (int)((E + 255) / 256);

    // 0) dtype detection
    detect_idx_dtype<<<1, 256>>>((const int*)ei, 1024);

    // 1) degree + CSR build
    zero_counts_deg<<<(n + 255) / 256, 256>>>(n);
    histo_deg<<<eb, 256>>>(ei, ew, E);
    compute_dinv<<<(n + 255) / 256, 256>>>(n);
    scan_offsets<<<1, 1024>>>(n);
    scatter_edges<<<eb, 256>>>(ei, ew, E);

    // 2) pre-convert x + weights (row-major hi/lo split)
    long x4  = (long)n * NFEAT / 4;
    long w14 = (long)NFEAT * F / 4;
    long w24 = (long)F * F / 4;
    convert_split<<<(int)((x4 + 255) / 256), 256>>>(x,  xh,  xl,  x4);
    convert_split<<<(int)((w14 + 255) / 256), 256>>>(W1, w1h, w1l, w14);
    convert_split<<<(int)((w24 + 255) / 256), 256>>>(W2, w2h, w2l, w24);

    dim3 gg((n + 127) / 128, F / 128);
    int gatherBlocks = (n * 32 + 255) / 256;

    // 3) layer 1: GEMM -> gather (writes relu-split bf16 directly)
    gemm_bf16x3<<<gg, 256>>>(n, F, NFEAT, xh, xl, w1h, w1l, h1);
    gather_agg<1><<<gatherBlocks, 256>>>(h1, b1, nullptr, a1h, a1l, n);

    // 4) layer 2: GEMM -> gather (writes relu'd fp32 agg2)
    gemm_bf16x3<<<gg, 256>>>(n, F, F, a1h, a1l, w2h, w2l, h2);
    gather_agg<0><<<gatherBlocks, 256>>>(h2, b2, agg2, nullptr, nullptr, n);

    // 5) BN stats + fused BN/LN
    bn_zero<<<1, F>>>();
    const int RPB = 128;
    bn_stats<<<(n + RPB - 1) / RPB, F>>>(agg2, n, RPB);
    bn_ln_final<<<n, F>>>(agg2, bg, bb, lg, lb, out, n);
}

// round 8
// speedup vs baseline: 2.0174x; 1.0145x over previous
#include <cuda_runtime.h>
#include <cuda_bf16.h>
#include <stdint.h>

#define N_NODES 50000
#define F 256
#define NFEAT 1024
#define E_MAX 800000
#define EPSV 1e-5f
typedef __nv_bfloat16 BF16;

// ---------------- scratch (__device__ globals) ----------------
__device__ float g_h1  [(size_t)N_NODES * F];
__device__ float g_h2  [(size_t)N_NODES * F];
__device__ float g_agg2[(size_t)N_NODES * F];
__device__ BF16 g_xh[(size_t)N_NODES * NFEAT];
__device__ BF16 g_xl[(size_t)N_NODES * NFEAT];
__device__ BF16 g_a1h[(size_t)N_NODES * F];
__device__ BF16 g_a1l[(size_t)N_NODES * F];
__device__ BF16 g_w1h[NFEAT * F], g_w1l[NFEAT * F];
__device__ BF16 g_w2h[F * F],     g_w2l[F * F];
__device__ float g_deg [N_NODES];
__device__ float g_dinv[N_NODES];
__device__ int   g_counts [N_NODES];
__device__ int   g_offsets[N_NODES + 1];
__device__ int   g_cursor [N_NODES];
__device__ uint2 g_epack  [E_MAX];          // (src, norm-weight)
__device__ float g_bnsum[F];
__device__ float g_bnssq[F];
__device__ int   g_is64;

// ---------------- edge_index dtype detection ----------------
__global__ void detect_idx_dtype(const int* ei32, int n_check) {
    __shared__ int bad;
    if (threadIdx.x == 0) bad = 0;
    __syncthreads();
    for (int i = threadIdx.x; i < n_check; i += blockDim.x)
        if (ei32[2 * i + 1] != 0) bad = 1;
    __syncthreads();
    if (threadIdx.x == 0) g_is64 = bad ? 0 : 1;
}

__device__ __forceinline__ long ld_idx(const void* ei, long i) {
    return g_is64 ? (long)((const long long*)ei)[i] : (long)((const int*)ei)[i];
}

// ---------------- degree + CSR ----------------
__global__ void zero_counts_deg(int n) {
    int i = blockIdx.x * blockDim.x + threadIdx.x;
    if (i < n) { g_counts[i] = 0; g_deg[i] = 1.0f; }
}

__global__ void histo_deg(const void* ei, const float* w, long E) {
    long e = blockIdx.x * (long)blockDim.x + threadIdx.x;
    if (e >= E) return;
    long dst = ld_idx(ei, E + e);
    atomicAdd(&g_deg[dst], w[e]);
    atomicAdd(&g_counts[(int)dst], 1);
}

__global__ void compute_dinv(int n) {
    int i = blockIdx.x * blockDim.x + threadIdx.x;
    if (i < n) {
        float d = g_deg[i];
        g_dinv[i] = d > 0.0f ? rsqrtf(fmaxf(d, 1e-30f)) : 0.0f;
    }
}

__global__ __launch_bounds__(1024) void scan_offsets(int n) {
    __shared__ int ssum[1024];
    int t = threadIdx.x;
    int chunk = (n + 1023) / 1024;
    int beg = t * chunk, end = min(beg + chunk, n);
    int s = 0;
    for (int i = beg; i < end; i++) s += g_counts[i];
    ssum[t] = s;
    __syncthreads();
    for (int o = 1; o < 1024; o <<= 1) {
        int u = (t >= o) ? ssum[t - o] : 0;
        __syncthreads();
        ssum[t] += u;
        __syncthreads();
    }
    int run = ssum[t] - s;
    for (int i = beg; i < end; i++) {
        g_offsets[i] = run;
        g_cursor[i]  = run;
        run += g_counts[i];
    }
    if (t == 1023) g_offsets[n] = run;
}

__global__ void scatter_edges(const void* ei, const float* w, long E) {
    long e = blockIdx.x * (long)blockDim.x + threadIdx.x;
    if (e >= E) return;
    long src = ld_idx(ei, e);
    long dst = ld_idx(ei, E + e);
    float nw = g_dinv[src] * w[e] * g_dinv[dst];
    int pos = atomicAdd(&g_cursor[(int)dst], 1);
    g_epack[pos] = make_uint2((unsigned)src, __float_as_uint(nw));
}

// ---------------- fp32 -> bf16 hi/lo split ----------------
__device__ __forceinline__ unsigned pk(BF16 lo, BF16 hi) {
    __nv_bfloat162 t = __halves2bfloat162(lo, hi);
    return *reinterpret_cast<unsigned*>(&t);
}

__global__ void convert_split(const float* __restrict__ in,
                              BF16* __restrict__ hi, BF16* __restrict__ lo,
                              long n4) {
    long i = blockIdx.x * (long)blockDim.x + threadIdx.x;
    if (i >= n4) return;
    float4 v = ((const float4*)in)[i];
    BF16 h0 = __float2bfloat16_rn(v.x), h1 = __float2bfloat16_rn(v.y);
    BF16 h2 = __float2bfloat16_rn(v.z), h3 = __float2bfloat16_rn(v.w);
    BF16 l0 = __float2bfloat16_rn(v.x - __bfloat162float(h0));
    BF16 l1 = __float2bfloat16_rn(v.y - __bfloat162float(h1));
    BF16 l2 = __float2bfloat16_rn(v.z - __bfloat162float(h2));
    BF16 l3 = __float2bfloat16_rn(v.w - __bfloat162float(h3));
    ((uint2*)hi)[i] = make_uint2(pk(h0, h1), pk(h2, h3));
    ((uint2*)lo)[i] = make_uint2(pk(l0, l1), pk(l2, l3));
}

// ---------------- mma helpers ----------------
__device__ __forceinline__ uint32_t s2u(const void* p) {
    return (uint32_t)__cvta_generic_to_shared(p);
}

__device__ __forceinline__ void ldsm_x4(unsigned* r, const void* p) {
    unsigned a = (unsigned)__cvta_generic_to_shared(p);
    asm volatile("ldmatrix.sync.aligned.m8n8.x4.shared.b16 {%0,%1,%2,%3}, [%4];"
                 : "=r"(r[0]), "=r"(r[1]), "=r"(r[2]), "=r"(r[3]) : "r"(a));
}

__device__ __forceinline__ void ldsm_x4_t(unsigned* r, const void* p) {
    unsigned a = (unsigned)__cvta_generic_to_shared(p);
    asm volatile("ldmatrix.sync.aligned.m8n8.x4.trans.shared.b16 {%0,%1,%2,%3}, [%4];"
                 : "=r"(r[0]), "=r"(r[1]), "=r"(r[2]), "=r"(r[3]) : "r"(a));
}

__device__ __forceinline__ void mma_bf16(float* d, const unsigned* a, const unsigned* b) {
    asm volatile(
        "mma.sync.aligned.m16n8k16.row.col.f32.bf16.bf16.f32 "
        "{%0,%1,%2,%3}, {%4,%5,%6,%7}, {%8,%9}, {%0,%1,%2,%3};"
        : "+f"(d[0]), "+f"(d[1]), "+f"(d[2]), "+f"(d[3])
        : "r"(a[0]), "r"(a[1]), "r"(a[2]), "r"(a[3]), "r"(b[0]), "r"(b[1]));
}

__device__ __forceinline__ void cpa16(uint32_t dst, const void* src, int srcbytes) {
    asm volatile("cp.async.cg.shared.global [%0], [%1], 16, %2;"
                 :: "r"(dst), "l"(src), "r"(srcbytes));
}

#define CP_COMMIT() asm volatile("cp.async.commit_group;" ::: "memory")
#define CP_WAIT1()  asm volatile("cp.async.wait_group 1;" ::: "memory")

// ---------------- cp.async 3-stage tensor-core GEMM (bf16x3) ----------------
// C[M,N] = (Ah+Al)[M,K] @ (Bh+Bl)[K,N], writes H. Block tile 128x128x32.
// Stage layout (bytes): Ah@0 (10240), Al@10240, Bh@20480 (8704), Bl@29184.
#define STAGE_BYTES 37888
#define GEMM_DSMEM  (3 * STAGE_BYTES)

__global__ __launch_bounds__(256, 1) void gemm_bf16x3(
    int M, int N, int K,
    const BF16* __restrict__ AH, const BF16* __restrict__ AL,
    const BF16* __restrict__ BH, const BF16* __restrict__ BL,
    float* __restrict__ H)
{
    extern __shared__ __align__(16) char dynsm[];
    const int tid = threadIdx.x, lane = tid & 31, warp = tid >> 5;
    const int wm = warp >> 2, wn = warp & 3;
    const int bRow = blockIdx.x, bCol = blockIdx.y;
    const int nk = K / 32;

    // cp.async coords: A 128rows x 4 chunks(16B), 2 chunks/thread
    const int ar  = tid >> 1;            // 0..127
    const int ac0 = (tid & 1) * 2;       // 0 or 2 (chunk)
    // B 32rows x 16 chunks, 2 chunks/thread
    const int br  = tid >> 3;            // 0..31
    const int bc0 = (tid & 7) * 2;       // 0..14

    const int gra  = bRow * 128 + ar;
    const int grac = min(gra, M - 1);
    const int asz  = (gra < M) ? 16 : 0;
    const char* gA  = (const char*)(AH + (size_t)grac * K);
    const char* gAl = (const char*)(AL + (size_t)grac * K);
    const char* gB  = (const char*)(BH + (size_t)br * N + bCol * 128);
    const char* gBl = (const char*)(BL + (size_t)br * N + bCol * 128);

    auto issue = [&](int kb, int s) {
        char* base = dynsm + s * STAGE_BYTES;
        const char* pa  = gA  + (size_t)kb * 64;    // kb*32 bf16 = 64 bytes
        const char* pal = gAl + (size_t)kb * 64;
        uint32_t sa  = s2u(base + ar * 80);
        uint32_t sal = s2u(base + 10240 + ar * 80);
        cpa16(sa  + ac0 * 16,       pa  + ac0 * 16,       asz);
        cpa16(sa  + (ac0 + 1) * 16, pa  + (ac0 + 1) * 16, asz);
        cpa16(sal + ac0 * 16,       pal + ac0 * 16,       asz);
        cpa16(sal + (ac0 + 1) * 16, pal + (ac0 + 1) * 16, asz);
        const char* pb  = gB  + (size_t)kb * 32 * N * 2;  // kb*32 rows of N bf16
        const char* pbl = gBl + (size_t)kb * 32 * N * 2;
        uint32_t sb  = s2u(base + 20480 + br * 272);
        uint32_t sbl = s2u(base + 29184 + br * 272);
        cpa16(sb  + bc0 * 16,       pb  + bc0 * 16,       16);
        cpa16(sb  + (bc0 + 1) * 16, pb  + (bc0 + 1) * 16, 16);
        cpa16(sbl + bc0 * 16,       pbl + bc0 * 16,       16);
        cpa16(sbl + (bc0 + 1) * 16, pbl + (bc0 + 1) * 16, 16);
    };

    float acc[4][4][4];
#pragma unroll
    for (int mi = 0; mi < 4; mi++)
#pragma unroll
        for (int nj = 0; nj < 4; nj++)
#pragma unroll
            for (int r = 0; r < 4; r++) acc[mi][nj][r] = 0.f;

    issue(0, 0); CP_COMMIT();
    if (nk > 1) issue(1, 1);
    CP_COMMIT();

    const int g8  = lane & 7;
    const int m01 = (lane >> 3) & 1;
    const int m23 = lane >> 4;

    for (int kb = 0; kb < nk; kb++) {
        const int s = kb % 3;
        CP_WAIT1();
        __syncthreads();

        unsigned short* Ahp = (unsigned short*)(dynsm + s * STAGE_BYTES);
        unsigned short* Alp = (unsigned short*)(dynsm + s * STAGE_BYTES + 10240);
        unsigned short* Bhp = (unsigned short*)(dynsm + s * STAGE_BYTES + 20480);
        unsigned short* Blp = (unsigned short*)(dynsm + s * STAGE_BYTES + 29184);

#pragma unroll
        for (int kk = 0; kk < 2; kk++) {
            const int k0 = kk * 16;
            unsigned aFh[4][4], aFl[4][4], bFh[4][2], bFl[4][2];
#pragma unroll
            for (int mi = 0; mi < 4; mi++) {
                int row = wm * 64 + mi * 16 + g8 + m01 * 8;
                int kof = k0 + m23 * 8;
                ldsm_x4(aFh[mi], &Ahp[row * 40 + kof]);
                ldsm_x4(aFl[mi], &Alp[row * 40 + kof]);
            }
#pragma unroll
            for (int bj = 0; bj < 2; bj++) {
                int krow = k0 + g8 + m01 * 8;
                int ncol = wn * 32 + bj * 16 + m23 * 8;
                unsigned t[4];
                ldsm_x4_t(t, &Bhp[krow * 136 + ncol]);
                bFh[2 * bj][0] = t[0]; bFh[2 * bj][1] = t[1];
                bFh[2 * bj + 1][0] = t[2]; bFh[2 * bj + 1][1] = t[3];
                ldsm_x4_t(t, &Blp[krow * 136 + ncol]);
                bFl[2 * bj][0] = t[0]; bFl[2 * bj][1] = t[1];
                bFl[2 * bj + 1][0] = t[2]; bFl[2 * bj + 1][1] = t[3];
            }
#pragma unroll
            for (int mi = 0; mi < 4; mi++)
#pragma unroll
                for (int nj = 0; nj < 4; nj++) {
                    mma_bf16(acc[mi][nj], aFh[mi], bFh[nj]);
                    mma_bf16(acc[mi][nj], aFh[mi], bFl[nj]);
                    mma_bf16(acc[mi][nj], aFl[mi], bFh[nj]);
                }
        }

        int nkb = kb + 2;
        if (nkb < nk) issue(nkb, nkb % 3);
        CP_COMMIT();
    }

    const int gg = lane >> 2, cc = lane & 3;
#pragma unroll
    for (int mi = 0; mi < 4; mi++) {
        int rb = bRow * 128 + wm * 64 + mi * 16;
        int r0 = rb + gg, r1 = rb + gg + 8;
#pragma unroll
        for (int nj = 0; nj < 4; nj++) {
            int col = bCol * 128 + wn * 32 + nj * 8 + 2 * cc;
            float* a = acc[mi][nj];
            if (r0 < M) *(float2*)(H + (size_t)r0 * N + col) = make_float2(a[0], a[1]);
            if (r1 < M) *(float2*)(H + (size_t)r1 * N + col) = make_float2(a[2], a[3]);
        }
    }
}

// ---------------- CSR gather aggregation (atomic-free, 2-edge unrolled) ----------------
template <int MODE>
__global__ __launch_bounds__(256) void gather_agg(
    const float* __restrict__ h, const float* __restrict__ bias,
    float* __restrict__ AGGF, BF16* __restrict__ AHo, BF16* __restrict__ ALo,
    int M)
{
    int warp = (blockIdx.x * blockDim.x + threadIdx.x) >> 5;
    int lane = threadIdx.x & 31;
    if (warp >= M) return;
    int dst = warp;
    int beg = g_offsets[dst], end = g_offsets[dst + 1];

    float4 s0a = make_float4(0.f, 0.f, 0.f, 0.f);
    float4 s0b = make_float4(0.f, 0.f, 0.f, 0.f);
    float4 s1a = make_float4(0.f, 0.f, 0.f, 0.f);
    float4 s1b = make_float4(0.f, 0.f, 0.f, 0.f);

    int e = beg;
    for (; e + 2 <= end; e += 2) {
        uint2 p0 = g_epack[e];
        uint2 p1 = g_epack[e + 1];
        float w0 = __uint_as_float(p0.y);
        float w1 = __uint_as_float(p1.y);
        const float4* q0 = (const float4*)(h + (size_t)p0.x * F);
        const float4* q1 = (const float4*)(h + (size_t)p1.x * F);
        float4 u00 = q0[lane], u01 = q0[lane + 32];
        float4 u10 = q1[lane], u11 = q1[lane + 32];
        s0a.x += w0 * u00.x; s0a.y += w0 * u00.y; s0a.z += w0 * u00.z; s0a.w += w0 * u00.w;
        s0b.x += w0 * u01.x; s0b.y += w0 * u01.y; s0b.z += w0 * u01.z; s0b.w += w0 * u01.w;
        s1a.x += w1 * u10.x; s1a.y += w1 * u10.y; s1a.z += w1 * u10.z; s1a.w += w1 * u10.w;
        s1b.x += w1 * u11.x; s1b.y += w1 * u11.y; s1b.z += w1 * u11.z; s1b.w += w1 * u11.w;
    }
    if (e < end) {
        uint2 p0 = g_epack[e];
        float w0 = __uint_as_float(p0.y);
        const float4* q0 = (const float4*)(h + (size_t)p0.x * F);
        float4 u00 = q0[lane], u01 = q0[lane + 32];
        s0a.x += w0 * u00.x; s0a.y += w0 * u00.y; s0a.z += w0 * u00.z; s0a.w += w0 * u00.w;
        s0b.x += w0 * u01.x; s0b.y += w0 * u01.y; s0b.z += w0 * u01.z; s0b.w += w0 * u01.w;
    }

    float di = g_dinv[dst], s = di * di;
    const float4* hd = (const float4*)(h + (size_t)dst * F);
    const float4* bp = (const float4*)bias;
    float4 u0 = hd[lane], u1 = hd[lane + 32];
    float4 b0 = bp[lane], b1 = bp[lane + 32];
    float4 o0, o1;
    o0.x = fmaxf(b0.x + s * u0.x + s0a.x + s1a.x, 0.f);
    o0.y = fmaxf(b0.y + s * u0.y + s0a.y + s1a.y, 0.f);
    o0.z = fmaxf(b0.z + s * u0.z + s0a.z + s1a.z, 0.f);
    o0.w = fmaxf(b0.w + s * u0.w + s0a.w + s1a.w, 0.f);
    o1.x = fmaxf(b1.x + s * u1.x + s0b.x + s1b.x, 0.f);
    o1.y = fmaxf(b1.y + s * u1.y + s0b.y + s1b.y, 0.f);
    o1.z = fmaxf(b1.z + s * u1.z + s0b.z + s1b.z, 0.f);
    o1.w = fmaxf(b1.w + s * u1.w + s0b.w + s1b.w, 0.f);

    if (MODE == 0) {
        float4* ap = (float4*)(AGGF + (size_t)dst * F);
        ap[lane] = o0;
        ap[lane + 32] = o1;
    } else {
        BF16 h0 = __float2bfloat16_rn(o0.x), h1 = __float2bfloat16_rn(o0.y);
        BF16 h2 = __float2bfloat16_rn(o0.z), h3 = __float2bfloat16_rn(o0.w);
        BF16 l0 = __float2bfloat16_rn(o0.x - __bfloat162float(h0));
        BF16 l1 = __float2bfloat16_rn(o0.y - __bfloat162float(h1));
        BF16 l2 = __float2bfloat16_rn(o0.z - __bfloat162float(h2));
        BF16 l3 = __float2bfloat16_rn(o0.w - __bfloat162float(h3));
        BF16 h4 = __float2bfloat16_rn(o1.x), h5 = __float2bfloat16_rn(o1.y);
        BF16 h6 = __float2bfloat16_rn(o1.z), h7 = __float2bfloat16_rn(o1.w);
        BF16 l4 = __float2bfloat16_rn(o1.x - __bfloat162float(h4));
        BF16 l5 = __float2bfloat16_rn(o1.y - __bfloat162float(h5));
        BF16 l6 = __float2bfloat16_rn(o1.z - __bfloat162float(h6));
        BF16 l7 = __float2bfloat16_rn(o1.w - __bfloat162float(h7));
        uint2* ph = (uint2*)(AHo + (size_t)dst * F);
        uint2* pl = (uint2*)(ALo + (size_t)dst * F);
        ph[lane]      = make_uint2(pk(h0, h1), pk(h2, h3));
        ph[lane + 32] = make_uint2(pk(h4, h5), pk(h6, h7));
        pl[lane]      = make_uint2(pk(l0, l1), pk(l2, l3));
        pl[lane + 32] = make_uint2(pk(l4, l5), pk(l6, l7));
    }
}

// ---------------- BN stats over agg2 (already relu'd) ----------------
__global__ void bn_zero() {
    int f = threadIdx.x;
    g_bnsum[f] = 0.0f;
    g_bnssq[f] = 0.0f;
}

__global__ void bn_stats(const float* __restrict__ agg2, int M, int rows_per_block) {
    int f = threadIdx.x;
    long r0 = blockIdx.x * (long)rows_per_block;
    long r1 = r0 + rows_per_block; if (r1 > M) r1 = M;
    float s = 0.f, ss = 0.f;
    for (long r = r0; r < r1; r++) {
        float v = agg2[r * F + f];
        s += v; ss += v * v;
    }
    atomicAdd(&g_bnsum[f], s);
    atomicAdd(&g_bnssq[f], ss);
}

// ---------------- fused BN + LN ----------------
__global__ void bn_ln_final(const float* __restrict__ agg2,
                            const float* __restrict__ bg, const float* __restrict__ bb,
                            const float* __restrict__ lg, const float* __restrict__ lb,
                            float* __restrict__ out, int M) {
    long r = blockIdx.x;
    int  f = threadIdx.x;
    int  lane = f & 31, wid = f >> 5;
    float invM = 1.0f / (float)M;

    float mu  = g_bnsum[f] * invM;
    float var = g_bnssq[f] * invM - mu * mu;
    float v = agg2[r * F + f];
    float y = (v - mu) * rsqrtf(var + EPSV) * bg[f] + bb[f];

    float s = y, ss = y * y;
#pragma unroll
    for (int o = 16; o > 0; o >>= 1) {
        s  += __shfl_xor_sync(0xffffffffu, s,  o);
        ss += __shfl_xor_sync(0xffffffffu, ss, o);
    }
    __shared__ float reds[8], redss[8];
    if (lane == 0) { reds[wid] = s; redss[wid] = ss; }
    __syncthreads();
    if (wid == 0) {
        float a = lane < 8 ? reds[lane]  : 0.f;
        float b = lane < 8 ? redss[lane] : 0.f;
#pragma unroll
        for (int o = 4; o > 0; o >>= 1) {
            a += __shfl_xor_sync(0xffffffffu, a, o);
            b += __shfl_xor_sync(0xffffffffu, b, o);
        }
        if (lane == 0) { reds[0] = a; redss[0] = b; }
    }
    __syncthreads();
    float lmu  = reds[0]  * (1.0f / F);
    float lvar = redss[0] * (1.0f / F) - lmu * lmu;
    out[r * F + f] = (y - lmu) * rsqrtf(lvar + EPSV) * lg[f] + lb[f];
}

// ---------------- launcher ----------------
extern "C" void kernel_launch(void* const* d_in, const int* in_sizes, int n_in,
                              void* d_out, int out_size) {
    const float* x  = (const float*)d_in[0];
    const void*  ei = d_in[1];
    const float* ew = (const float*)d_in[2];
    const float* W1 = (const float*)d_in[3];
    const float* b1 = (const float*)d_in[4];
    const float* W2 = (const float*)d_in[5];
    const float* b2 = (const float*)d_in[6];
    const float* bg = (const float*)d_in[7];
    const float* bb = (const float*)d_in[8];
    const float* lg = (const float*)d_in[9];
    const float* lb = (const float*)d_in[10];
    float* out = (float*)d_out;

    int  n = in_sizes[0] / NFEAT;            // 50000
    long E = in_sizes[1] / 2;                // 800000
    if (E > E_MAX) E = E_MAX;

    float* h1;   cudaGetSymbolAddress((void**)&h1,   g_h1);
    float* h2;   cudaGetSymbolAddress((void**)&h2,   g_h2);
    float* agg2; cudaGetSymbolAddress((void**)&agg2, g_agg2);
    BF16 *xh, *xl, *a1h, *a1l, *w1h, *w1l, *w2h, *w2l;
    cudaGetSymbolAddress((void**)&xh,  g_xh);
    cudaGetSymbolAddress((void**)&xl,  g_xl);
    cudaGetSymbolAddress((void**)&a1h, g_a1h);
    cudaGetSymbolAddress((void**)&a1l, g_a1l);
    cudaGetSymbolAddress((void**)&w1h, g_w1h);
    cudaGetSymbolAddress((void**)&w1l, g_w1l);
    cudaGetSymbolAddress((void**)&w2h, g_w2h);
    cudaGetSymbolAddress((void**)&w2l, g_w2l);

    cudaFuncSetAttribute(gemm_bf16x3,
                         cudaFuncAttributeMaxDynamicSharedMemorySize, GEMM_DSMEM);

    int eb = (int)((E + 255) / 256);
    long x4  = (long)n * NFEAT / 4;
    long w14 = (long)NFEAT * F / 4;
    long w24 = (long)F * F / 4;
    dim3 gg((n + 127) / 128, F / 128);
    int gatherBlocks = (n * 32 + 255) / 256;

    // ---- launches 0-2: converts (gemm1 prereqs) ----
    convert_split<<<(int)((x4 + 255) / 256), 256>>>(x,  xh,  xl,  x4);
    convert_split<<<(int)((w14 + 255) / 256), 256>>>(W1, w1h, w1l, w14);
    convert_split<<<(int)((w24 + 255) / 256), 256>>>(W2, w2h, w2l, w24);

    // ---- launch 3: GEMM1 (positioned at the ncu capture slot) ----
    gemm_bf16x3<<<gg, 256, GEMM_DSMEM>>>(n, F, NFEAT, xh, xl, w1h, w1l, h1);

    // ---- CSR + degree chain (independent of GEMM1) ----
    detect_idx_dtype<<<1, 256>>>((const int*)ei, 1024);
    zero_counts_deg<<<(n + 255) / 256, 256>>>(n);
    histo_deg<<<eb, 256>>>(ei, ew, E);
    compute_dinv<<<(n + 255) / 256, 256>>>(n);
    scan_offsets<<<1, 1024>>>(n);
    scatter_edges<<<eb, 256>>>(ei, ew, E);

    // ---- layer 1 aggregation (writes relu-split bf16 directly) ----
    gather_agg<1><<<gatherBlocks, 256>>>(h1, b1, nullptr, a1h, a1l, n);

    // ---- layer 2 ----
    gemm_bf16x3<<<gg, 256, GEMM_DSMEM>>>(n, F, F, a1h, a1l, w2h, w2l, h2);
    gather_agg<0><<<gatherBlocks, 256>>>(h2, b2, agg2, nullptr, nullptr, n);

    // ---- BN stats + fused BN/LN ----
    bn_zero<<<1, F>>>();
    const int RPB = 128;
    bn_stats<<<(n + RPB - 1) / RPB, F>>>(agg2, n, RPB);
    bn_ln_final<<<n, F>>>(agg2, bg, bb, lg, lb, out, n);
}

// round 10
// speedup vs baseline: 2.0437x; 1.0131x over previous
#include <cuda_runtime.h>
#include <cuda_bf16.h>
#include <stdint.h>

#define N_NODES 50000
#define F 256
#define NFEAT 1024
#define E_MAX 800000
#define EPSV 1e-5f
typedef __nv_bfloat16 BF16;

// ---------------- scratch (__device__ globals) ----------------
__device__ float g_h1  [(size_t)N_NODES * F];
__device__ float g_h2  [(size_t)N_NODES * F];
__device__ float g_agg2[(size_t)N_NODES * F];
__device__ BF16 g_xh[(size_t)N_NODES * NFEAT];
__device__ BF16 g_xl[(size_t)N_NODES * NFEAT];
__device__ BF16 g_a1h[(size_t)N_NODES * F];
__device__ BF16 g_a1l[(size_t)N_NODES * F];
__device__ BF16 g_w1h[NFEAT * F], g_w1l[NFEAT * F];
__device__ BF16 g_w2h[F * F],     g_w2l[F * F];
__device__ float g_deg [N_NODES];
__device__ float g_dinv[N_NODES];
__device__ int   g_counts [N_NODES];
__device__ int   g_offsets[N_NODES + 1];
__device__ int   g_cursor [N_NODES];
__device__ uint2 g_epack  [E_MAX];          // (src, norm-weight)
__device__ float g_bnsum[F];
__device__ float g_bnssq[F];
__device__ int   g_is64;

// ---------------- edge_index dtype detection ----------------
__global__ void detect_idx_dtype(const int* ei32, int n_check) {
    __shared__ int bad;
    if (threadIdx.x == 0) bad = 0;
    __syncthreads();
    for (int i = threadIdx.x; i < n_check; i += blockDim.x)
        if (ei32[2 * i + 1] != 0) bad = 1;
    __syncthreads();
    if (threadIdx.x == 0) g_is64 = bad ? 0 : 1;
}

__device__ __forceinline__ long ld_idx(const void* ei, long i) {
    return g_is64 ? (long)((const long long*)ei)[i] : (long)((const int*)ei)[i];
}

// ---------------- degree + CSR ----------------
__global__ void zero_counts_deg(int n) {
    int i = blockIdx.x * blockDim.x + threadIdx.x;
    if (i < n) { g_counts[i] = 0; g_deg[i] = 1.0f; }
}

__global__ void histo_deg(const void* ei, const float* w, long E) {
    long e = blockIdx.x * (long)blockDim.x + threadIdx.x;
    if (e >= E) return;
    long dst = ld_idx(ei, E + e);
    atomicAdd(&g_deg[dst], w[e]);
    atomicAdd(&g_counts[(int)dst], 1);
}

__global__ void compute_dinv(int n) {
    int i = blockIdx.x * blockDim.x + threadIdx.x;
    if (i < n) {
        float d = g_deg[i];
        g_dinv[i] = d > 0.0f ? rsqrtf(fmaxf(d, 1e-30f)) : 0.0f;
    }
}

__global__ __launch_bounds__(1024) void scan_offsets(int n) {
    __shared__ int ssum[1024];
    int t = threadIdx.x;
    int chunk = (n + 1023) / 1024;
    int beg = t * chunk, end = min(beg + chunk, n);
    int s = 0;
    for (int i = beg; i < end; i++) s += g_counts[i];
    ssum[t] = s;
    __syncthreads();
    for (int o = 1; o < 1024; o <<= 1) {
        int u = (t >= o) ? ssum[t - o] : 0;
        __syncthreads();
        ssum[t] += u;
        __syncthreads();
    }
    int run = ssum[t] - s;
    for (int i = beg; i < end; i++) {
        g_offsets[i] = run;
        g_cursor[i]  = run;
        run += g_counts[i];
    }
    if (t == 1023) g_offsets[n] = run;
}

__global__ void scatter_edges(const void* ei, const float* w, long E) {
    long e = blockIdx.x * (long)blockDim.x + threadIdx.x;
    if (e >= E) return;
    long src = ld_idx(ei, e);
    long dst = ld_idx(ei, E + e);
    float nw = g_dinv[src] * w[e] * g_dinv[dst];
    int pos = atomicAdd(&g_cursor[(int)dst], 1);
    g_epack[pos] = make_uint2((unsigned)src, __float_as_uint(nw));
}

// ---------------- fp32 -> bf16 hi/lo split ----------------
__device__ __forceinline__ unsigned pk(BF16 lo, BF16 hi) {
    __nv_bfloat162 t = __halves2bfloat162(lo, hi);
    return *reinterpret_cast<unsigned*>(&t);
}

__global__ void convert_split(const float* __restrict__ in,
                              BF16* __restrict__ hi, BF16* __restrict__ lo,
                              long n4) {
    long i = blockIdx.x * (long)blockDim.x + threadIdx.x;
    if (i >= n4) return;
    float4 v = ((const float4*)in)[i];
    BF16 h0 = __float2bfloat16_rn(v.x), h1 = __float2bfloat16_rn(v.y);
    BF16 h2 = __float2bfloat16_rn(v.z), h3 = __float2bfloat16_rn(v.w);
    BF16 l0 = __float2bfloat16_rn(v.x - __bfloat162float(h0));
    BF16 l1 = __float2bfloat16_rn(v.y - __bfloat162float(h1));
    BF16 l2 = __float2bfloat16_rn(v.z - __bfloat162float(h2));
    BF16 l3 = __float2bfloat16_rn(v.w - __bfloat162float(h3));
    ((uint2*)hi)[i] = make_uint2(pk(h0, h1), pk(h2, h3));
    ((uint2*)lo)[i] = make_uint2(pk(l0, l1), pk(l2, l3));
}

// ---------------- mma helpers ----------------
__device__ __forceinline__ uint32_t s2u(const void* p) {
    return (uint32_t)__cvta_generic_to_shared(p);
}

__device__ __forceinline__ void ldsm_x4(unsigned* r, const void* p) {
    unsigned a = (unsigned)__cvta_generic_to_shared(p);
    asm volatile("ldmatrix.sync.aligned.m8n8.x4.shared.b16 {%0,%1,%2,%3}, [%4];"
                 : "=r"(r[0]), "=r"(r[1]), "=r"(r[2]), "=r"(r[3]) : "r"(a));
}

__device__ __forceinline__ void ldsm_x4_t(unsigned* r, const void* p) {
    unsigned a = (unsigned)__cvta_generic_to_shared(p);
    asm volatile("ldmatrix.sync.aligned.m8n8.x4.trans.shared.b16 {%0,%1,%2,%3}, [%4];"
                 : "=r"(r[0]), "=r"(r[1]), "=r"(r[2]), "=r"(r[3]) : "r"(a));
}

__device__ __forceinline__ void mma_bf16(float* d, const unsigned* a, const unsigned* b) {
    asm volatile(
        "mma.sync.aligned.m16n8k16.row.col.f32.bf16.bf16.f32 "
        "{%0,%1,%2,%3}, {%4,%5,%6,%7}, {%8,%9}, {%0,%1,%2,%3};"
        : "+f"(d[0]), "+f"(d[1]), "+f"(d[2]), "+f"(d[3])
        : "r"(a[0]), "r"(a[1]), "r"(a[2]), "r"(a[3]), "r"(b[0]), "r"(b[1]));
}

__device__ __forceinline__ void cpa16(uint32_t dst, const void* src, int srcbytes) {
    asm volatile("cp.async.cg.shared.global [%0], [%1], 16, %2;"
                 :: "r"(dst), "l"(src), "r"(srcbytes));
}

#define CP_COMMIT() asm volatile("cp.async.commit_group;" ::: "memory")
#define CP_WAIT1()  asm volatile("cp.async.wait_group 1;" ::: "memory")

// ---------------- cp.async 3-stage tensor-core GEMM (bf16x3, 512 threads) ----------------
// C[M,N] = (Ah+Al)[M,K] @ (Bh+Bl)[K,N], writes H. Block tile 128x128x32.
// 16 warps in a 4x4 grid; each warp computes a 32x32 output tile.
// Stage layout (bytes): Ah@0 (10240), Al@10240, Bh@20480 (8704), Bl@29184.
#define STAGE_BYTES 37888
#define GEMM_DSMEM  (3 * STAGE_BYTES)

__global__ __launch_bounds__(512, 1) void gemm_bf16x3(
    int M, int N, int K,
    const BF16* __restrict__ AH, const BF16* __restrict__ AL,
    const BF16* __restrict__ BH, const BF16* __restrict__ BL,
    float* __restrict__ H)
{
    extern __shared__ __align__(16) char dynsm[];
    const int tid = threadIdx.x, lane = tid & 31, warp = tid >> 5;
    const int wm = warp >> 2, wn = warp & 3;       // 4x4 warp grid
    const int bRow = blockIdx.x, bCol = blockIdx.y;
    const int nk = K / 32;

    // cp.async coords: A 128 rows x 4 chunks(16B) = 512 -> 1 chunk/thread
    const int ar = tid >> 2;            // 0..127
    const int ac = tid & 3;             // 0..3
    // B 32 rows x 16 chunks = 512 -> 1 chunk/thread
    const int br = tid >> 4;            // 0..31
    const int bc = tid & 15;            // 0..15

    const int gra  = bRow * 128 + ar;
    const int grac = min(gra, M - 1);
    const int asz  = (gra < M) ? 16 : 0;
    const char* gA  = (const char*)(AH + (size_t)grac * K);
    const char* gAl = (const char*)(AL + (size_t)grac * K);
    const char* gB  = (const char*)(BH + (size_t)br * N + bCol * 128);
    const char* gBl = (const char*)(BL + (size_t)br * N + bCol * 128);

    auto issue = [&](int kb, int s) {
        char* base = dynsm + s * STAGE_BYTES;
        cpa16(s2u(base + ar * 80) + ac * 16,         gA  + (size_t)kb * 64 + ac * 16, asz);
        cpa16(s2u(base + 10240 + ar * 80) + ac * 16, gAl + (size_t)kb * 64 + ac * 16, asz);
        const char* pb  = gB  + (size_t)kb * 32 * N * 2;
        const char* pbl = gBl + (size_t)kb * 32 * N * 2;
        cpa16(s2u(base + 20480 + br * 272) + bc * 16, pb  + bc * 16, 16);
        cpa16(s2u(base + 29184 + br * 272) + bc * 16, pbl + bc * 16, 16);
    };

    float acc[2][4][4];
#pragma unroll
    for (int mi = 0; mi < 2; mi++)
#pragma unroll
        for (int nj = 0; nj < 4; nj++)
#pragma unroll
            for (int r = 0; r < 4; r++) acc[mi][nj][r] = 0.f;

    issue(0, 0); CP_COMMIT();
    if (nk > 1) issue(1, 1);
    CP_COMMIT();

    const int g8  = lane & 7;
    const int m01 = (lane >> 3) & 1;
    const int m23 = lane >> 4;

    for (int kb = 0; kb < nk; kb++) {
        const int s = kb % 3;
        CP_WAIT1();
        __syncthreads();

        unsigned short* Ahp = (unsigned short*)(dynsm + s * STAGE_BYTES);
        unsigned short* Alp = (unsigned short*)(dynsm + s * STAGE_BYTES + 10240);
        unsigned short* Bhp = (unsigned short*)(dynsm + s * STAGE_BYTES + 20480);
        unsigned short* Blp = (unsigned short*)(dynsm + s * STAGE_BYTES + 29184);

#pragma unroll
        for (int kk = 0; kk < 2; kk++) {
            const int k0 = kk * 16;
            unsigned aFh[2][4], aFl[2][4], bFh[4][2], bFl[4][2];
#pragma unroll
            for (int mi = 0; mi < 2; mi++) {
                int row = wm * 32 + mi * 16 + g8 + m01 * 8;
                int kof = k0 + m23 * 8;
                ldsm_x4(aFh[mi], &Ahp[row * 40 + kof]);
                ldsm_x4(aFl[mi], &Alp[row * 40 + kof]);
            }
#pragma unroll
            for (int bj = 0; bj < 2; bj++) {
                int krow = k0 + g8 + m01 * 8;
                int ncol = wn * 32 + bj * 16 + m23 * 8;
                unsigned t[4];
                ldsm_x4_t(t, &Bhp[krow * 136 + ncol]);
                bFh[2 * bj][0] = t[0]; bFh[2 * bj][1] = t[1];
                bFh[2 * bj + 1][0] = t[2]; bFh[2 * bj + 1][1] = t[3];
                ldsm_x4_t(t, &Blp[krow * 136 + ncol]);
                bFl[2 * bj][0] = t[0]; bFl[2 * bj][1] = t[1];
                bFl[2 * bj + 1][0] = t[2]; bFl[2 * bj + 1][1] = t[3];
            }
#pragma unroll
            for (int mi = 0; mi < 2; mi++)
#pragma unroll
                for (int nj = 0; nj < 4; nj++) {
                    mma_bf16(acc[mi][nj], aFh[mi], bFh[nj]);
                    mma_bf16(acc[mi][nj], aFh[mi], bFl[nj]);
                    mma_bf16(acc[mi][nj], aFl[mi], bFh[nj]);
                }
        }

        int nkb = kb + 2;
        if (nkb < nk) issue(nkb, nkb % 3);
        CP_COMMIT();
    }

    const int gg = lane >> 2, cc = lane & 3;
#pragma unroll
    for (int mi = 0; mi < 2; mi++) {
        int rb = bRow * 128 + wm * 32 + mi * 16;
        int r0 = rb + gg, r1 = rb + gg + 8;
#pragma unroll
        for (int nj = 0; nj < 4; nj++) {
            int col = bCol * 128 + wn * 32 + nj * 8 + 2 * cc;
            float* a = acc[mi][nj];
            if (r0 < M) *(float2*)(H + (size_t)r0 * N + col) = make_float2(a[0], a[1]);
            if (r1 < M) *(float2*)(H + (size_t)r1 * N + col) = make_float2(a[2], a[3]);
        }
    }
}

// ---------------- CSR gather aggregation (atomic-free, 2-edge unrolled) ----------------
template <int MODE>
__global__ __launch_bounds__(256) void gather_agg(
    const float* __restrict__ h, const float* __restrict__ bias,
    float* __restrict__ AGGF, BF16* __restrict__ AHo, BF16* __restrict__ ALo,
    int M)
{
    int warp = (blockIdx.x * blockDim.x + threadIdx.x) >> 5;
    int lane = threadIdx.x & 31;
    if (warp >= M) return;
    int dst = warp;
    int beg = g_offsets[dst], end = g_offsets[dst + 1];

    float4 s0a = make_float4(0.f, 0.f, 0.f, 0.f);
    float4 s0b = make_float4(0.f, 0.f, 0.f, 0.f);
    float4 s1a = make_float4(0.f, 0.f, 0.f, 0.f);
    float4 s1b = make_float4(0.f, 0.f, 0.f, 0.f);

    int e = beg;
    for (; e + 2 <= end; e += 2) {
        uint2 p0 = g_epack[e];
        uint2 p1 = g_epack[e + 1];
        float w0 = __uint_as_float(p0.y);
        float w1 = __uint_as_float(p1.y);
        const float4* q0 = (const float4*)(h + (size_t)p0.x * F);
        const float4* q1 = (const float4*)(h + (size_t)p1.x * F);
        float4 u00 = q0[lane], u01 = q0[lane + 32];
        float4 u10 = q1[lane], u11 = q1[lane + 32];
        s0a.x += w0 * u00.x; s0a.y += w0 * u00.y; s0a.z += w0 * u00.z; s0a.w += w0 * u00.w;
        s0b.x += w0 * u01.x; s0b.y += w0 * u01.y; s0b.z += w0 * u01.z; s0b.w += w0 * u01.w;
        s1a.x += w1 * u10.x; s1a.y += w1 * u10.y; s1a.z += w1 * u10.z; s1a.w += w1 * u10.w;
        s1b.x += w1 * u11.x; s1b.y += w1 * u11.y; s1b.z += w1 * u11.z; s1b.w += w1 * u11.w;
    }
    if (e < end) {
        uint2 p0 = g_epack[e];
        float w0 = __uint_as_float(p0.y);
        const float4* q0 = (const float4*)(h + (size_t)p0.x * F);
        float4 u00 = q0[lane], u01 = q0[lane + 32];
        s0a.x += w0 * u00.x; s0a.y += w0 * u00.y; s0a.z += w0 * u00.z; s0a.w += w0 * u00.w;
        s0b.x += w0 * u01.x; s0b.y += w0 * u01.y; s0b.z += w0 * u01.z; s0b.w += w0 * u01.w;
    }

    float di = g_dinv[dst], s = di * di;
    const float4* hd = (const float4*)(h + (size_t)dst * F);
    const float4* bp = (const float4*)bias;
    float4 u0 = hd[lane], u1 = hd[lane + 32];
    float4 b0 = bp[lane], b1 = bp[lane + 32];
    float4 o0, o1;
    o0.x = fmaxf(b0.x + s * u0.x + s0a.x + s1a.x, 0.f);
    o0.y = fmaxf(b0.y + s * u0.y + s0a.y + s1a.y, 0.f);
    o0.z = fmaxf(b0.z + s * u0.z + s0a.z + s1a.z, 0.f);
    o0.w = fmaxf(b0.w + s * u0.w + s0a.w + s1a.w, 0.f);
    o1.x = fmaxf(b1.x + s * u1.x + s0b.x + s1b.x, 0.f);
    o1.y = fmaxf(b1.y + s * u1.y + s0b.y + s1b.y, 0.f);
    o1.z = fmaxf(b1.z + s * u1.z + s0b.z + s1b.z, 0.f);
    o1.w = fmaxf(b1.w + s * u1.w + s0b.w + s1b.w, 0.f);

    if (MODE == 0) {
        float4* ap = (float4*)(AGGF + (size_t)dst * F);
        ap[lane] = o0;
        ap[lane + 32] = o1;
    } else {
        BF16 h0 = __float2bfloat16_rn(o0.x), h1 = __float2bfloat16_rn(o0.y);
        BF16 h2 = __float2bfloat16_rn(o0.z), h3 = __float2bfloat16_rn(o0.w);
        BF16 l0 = __float2bfloat16_rn(o0.x - __bfloat162float(h0));
        BF16 l1 = __float2bfloat16_rn(o0.y - __bfloat162float(h1));
        BF16 l2 = __float2bfloat16_rn(o0.z - __bfloat162float(h2));
        BF16 l3 = __float2bfloat16_rn(o0.w - __bfloat162float(h3));
        BF16 h4 = __float2bfloat16_rn(o1.x), h5 = __float2bfloat16_rn(o1.y);
        BF16 h6 = __float2bfloat16_rn(o1.z), h7 = __float2bfloat16_rn(o1.w);
        BF16 l4 = __float2bfloat16_rn(o1.x - __bfloat162float(h4));
        BF16 l5 = __float2bfloat16_rn(o1.y - __bfloat162float(h5));
        BF16 l6 = __float2bfloat16_rn(o1.z - __bfloat162float(h6));
        BF16 l7 = __float2bfloat16_rn(o1.w - __bfloat162float(h7));
        uint2* ph = (uint2*)(AHo + (size_t)dst * F);
        uint2* pl = (uint2*)(ALo + (size_t)dst * F);
        ph[lane]      = make_uint2(pk(h0, h1), pk(h2, h3));
        ph[lane + 32] = make_uint2(pk(h4, h5), pk(h6, h7));
        pl[lane]      = make_uint2(pk(l0, l1), pk(l2, l3));
        pl[lane + 32] = make_uint2(pk(l4, l5), pk(l6, l7));
    }
}

// ---------------- BN stats over agg2 (already relu'd) ----------------
__global__ void bn_zero() {
    int f = threadIdx.x;
    g_bnsum[f] = 0.0f;
    g_bnssq[f] = 0.0f;
}

__global__ void bn_stats(const float* __restrict__ agg2, int M, int rows_per_block) {
    int f = threadIdx.x;
    long r0 = blockIdx.x * (long)rows_per_block;
    long r1 = r0 + rows_per_block; if (r1 > M) r1 = M;
    float s = 0.f, ss = 0.f;
    for (long r = r0; r < r1; r++) {
        float v = agg2[r * F + f];
        s += v; ss += v * v;
    }
    atomicAdd(&g_bnsum[f], s);
    atomicAdd(&g_bnssq[f], ss);
}

// ---------------- fused BN + LN ----------------
__global__ void bn_ln_final(const float* __restrict__ agg2,
                            const float* __restrict__ bg, const float* __restrict__ bb,
                            const float* __restrict__ lg, const float* __restrict__ lb,
                            float* __restrict__ out, int M) {
    long r = blockIdx.x;
    int  f = threadIdx.x;
    int  lane = f & 31, wid = f >> 5;
    float invM = 1.0f / (float)M;

    float mu  = g_bnsum[f] * invM;
    float var = g_bnssq[f] * invM - mu * mu;
    float v = agg2[r * F + f];
    float y = (v - mu) * rsqrtf(var + EPSV) * bg[f] + bb[f];

    float s = y, ss = y * y;
#pragma unroll
    for (int o = 16; o > 0; o >>= 1) {
        s  += __shfl_xor_sync(0xffffffffu, s,  o);
        ss += __shfl_xor_sync(0xffffffffu, ss, o);
    }
    __shared__ float reds[8], redss[8];
    if (lane == 0) { reds[wid] = s; redss[wid] = ss; }
    __syncthreads();
    if (wid == 0) {
        float a = lane < 8 ? reds[lane]  : 0.f;
        float b = lane < 8 ? redss[lane] : 0.f;
#pragma unroll
        for (int o = 4; o > 0; o >>= 1) {
            a += __shfl_xor_sync(0xffffffffu, a, o);
            b += __shfl_xor_sync(0xffffffffu, b, o);
        }
        if (lane == 0) { reds[0] = a; redss[0] = b; }
    }
    __syncthreads();
    float lmu  = reds[0]  * (1.0f / F);
    float lvar = redss[0] * (1.0f / F) - lmu * lmu;
    out[r * F + f] = (y - lmu) * rsqrtf(lvar + EPSV) * lg[f] + lb[f];
}

// ---------------- launcher ----------------
extern "C" void kernel_launch(void* const* d_in, const int* in_sizes, int n_in,
                              void* d_out, int out_size) {
    const float* x  = (const float*)d_in[0];
    const void*  ei = d_in[1];
    const float* ew = (const float*)d_in[2];
    const float* W1 = (const float*)d_in[3];
    const float* b1 = (const float*)d_in[4];
    const float* W2 = (const float*)d_in[5];
    const float* b2 = (const float*)d_in[6];
    const float* bg = (const float*)d_in[7];
    const float* bb = (const float*)d_in[8];
    const float* lg = (const float*)d_in[9];
    const float* lb = (const float*)d_in[10];
    float* out = (float*)d_out;

    int  n = in_sizes[0] / NFEAT;            // 50000
    long E = in_sizes[1] / 2;                // 800000
    if (E > E_MAX) E = E_MAX;

    float* h1;   cudaGetSymbolAddress((void**)&h1,   g_h1);
    float* h2;   cudaGetSymbolAddress((void**)&h2,   g_h2);
    float* agg2; cudaGetSymbolAddress((void**)&agg2, g_agg2);
    BF16 *xh, *xl, *a1h, *a1l, *w1h, *w1l, *w2h, *w2l;
    cudaGetSymbolAddress((void**)&xh,  g_xh);
    cudaGetSymbolAddress((void**)&xl,  g_xl);
    cudaGetSymbolAddress((void**)&a1h, g_a1h);
    cudaGetSymbolAddress((void**)&a1l, g_a1l);
    cudaGetSymbolAddress((void**)&w1h, g_w1h);
    cudaGetSymbolAddress((void**)&w1l, g_w1l);
    cudaGetSymbolAddress((void**)&w2h, g_w2h);
    cudaGetSymbolAddress((void**)&w2l, g_w2l);

    cudaFuncSetAttribute(gemm_bf16x3,
                         cudaFuncAttributeMaxDynamicSharedMemorySize, GEMM_DSMEM);

    int eb = (int)((E + 255) / 256);
    long x4  = (long)n * NFEAT / 4;
    long w14 = (long)NFEAT * F / 4;
    long w24 = (long)F * F / 4;
    dim3 gg((n + 127) / 128, F / 128);
    int gatherBlocks = (n * 32 + 255) / 256;

    // ---- launches 0-2: converts (gemm1 prereqs) ----
    convert_split<<<(int)((x4 + 255) / 256), 256>>>(x,  xh,  xl,  x4);
    convert_split<<<(int)((w14 + 255) / 256), 256>>>(W1, w1h, w1l, w14);
    convert_split<<<(int)((w24 + 255) / 256), 256>>>(W2, w2h, w2l, w24);

    // ---- launch 3: GEMM1 (positioned at the ncu capture slot) ----
    gemm_bf16x3<<<gg, 512, GEMM_DSMEM>>>(n, F, NFEAT, xh, xl, w1h, w1l, h1);

    // ---- CSR + degree chain (independent of GEMM1) ----
    detect_idx_dtype<<<1, 256>>>((const int*)ei, 1024);
    zero_counts_deg<<<(n + 255) / 256, 256>>>(n);
    histo_deg<<<eb, 256>>>(ei, ew, E);
    compute_dinv<<<(n + 255) / 256, 256>>>(n);
    scan_offsets<<<1, 1024>>>(n);
    scatter_edges<<<eb, 256>>>(ei, ew, E);

    // ---- layer 1 aggregation (writes relu-split bf16 directly) ----
    gather_agg<1><<<gatherBlocks, 256>>>(h1, b1, nullptr, a1h, a1l, n);

    // ---- layer 2 ----
    gemm_bf16x3<<<gg, 512, GEMM_DSMEM>>>(n, F, F, a1h, a1l, w2h, w2l, h2);
    gather_agg<0><<<gatherBlocks, 256>>>(h2, b2, agg2, nullptr, nullptr, n);

    // ---- BN stats + fused BN/LN ----
    bn_zero<<<1, F>>>();
    const int RPB = 128;
    bn_stats<<<(n + RPB - 1) / RPB, F>>>(agg2, n, RPB);
    bn_ln_final<<<n, F>>>(agg2, bg, bb, lg, lb, out, n);
}

// round 11
// speedup vs baseline: 2.0544x; 1.0052x over previous
#include <cuda_runtime.h>
#include <cuda_bf16.h>
#include <stdint.h>

#define N_NODES 50000
#define F 256
#define NFEAT 1024
#define E_MAX 800000
#define EPSV 1e-5f
typedef __nv_bfloat16 BF16;

// ---------------- scratch (__device__ globals) ----------------
__device__ float g_h1  [(size_t)N_NODES * F];
__device__ float g_h2  [(size_t)N_NODES * F];
__device__ float g_agg2[(size_t)N_NODES * F];
__device__ BF16 g_xh[(size_t)N_NODES * NFEAT];
__device__ BF16 g_xl[(size_t)N_NODES * NFEAT];
__device__ BF16 g_a1h[(size_t)N_NODES * F];
__device__ BF16 g_a1l[(size_t)N_NODES * F];
__device__ BF16 g_w1h[NFEAT * F], g_w1l[NFEAT * F];
__device__ BF16 g_w2h[F * F],     g_w2l[F * F];
__device__ float g_deg [N_NODES];
__device__ float g_dinv[N_NODES];
__device__ int   g_counts [N_NODES];
__device__ int   g_offsets[N_NODES + 1];
__device__ int   g_cursor [N_NODES];
__device__ uint2 g_epack  [E_MAX];          // (src, norm-weight)
__device__ float g_bnsum[F];
__device__ float g_bnssq[F];
__device__ int   g_is64;

// ---------------- edge_index dtype detection ----------------
__global__ void detect_idx_dtype(const int* ei32, int n_check) {
    __shared__ int bad;
    if (threadIdx.x == 0) bad = 0;
    __syncthreads();
    for (int i = threadIdx.x; i < n_check; i += blockDim.x)
        if (ei32[2 * i + 1] != 0) bad = 1;
    __syncthreads();
    if (threadIdx.x == 0) g_is64 = bad ? 0 : 1;
}

__device__ __forceinline__ long ld_idx(const void* ei, long i) {
    return g_is64 ? (long)((const long long*)ei)[i] : (long)((const int*)ei)[i];
}

// ---------------- degree + CSR ----------------
__global__ void zero_counts_deg(int n) {
    int i = blockIdx.x * blockDim.x + threadIdx.x;
    if (i < n) { g_counts[i] = 0; g_deg[i] = 1.0f; }
}

__global__ void histo_deg(const void* ei, const float* w, long E) {
    long e = blockIdx.x * (long)blockDim.x + threadIdx.x;
    if (e >= E) return;
    long dst = ld_idx(ei, E + e);
    atomicAdd(&g_deg[dst], w[e]);
    atomicAdd(&g_counts[(int)dst], 1);
}

__global__ void compute_dinv(int n) {
    int i = blockIdx.x * blockDim.x + threadIdx.x;
    if (i < n) {
        float d = g_deg[i];
        g_dinv[i] = d > 0.0f ? rsqrtf(fmaxf(d, 1e-30f)) : 0.0f;
    }
}

__global__ __launch_bounds__(1024) void scan_offsets(int n) {
    __shared__ int ssum[1024];
    int t = threadIdx.x;
    int chunk = (n + 1023) / 1024;
    int beg = t * chunk, end = min(beg + chunk, n);
    int s = 0;
    for (int i = beg; i < end; i++) s += g_counts[i];
    ssum[t] = s;
    __syncthreads();
    for (int o = 1; o < 1024; o <<= 1) {
        int u = (t >= o) ? ssum[t - o] : 0;
        __syncthreads();
        ssum[t] += u;
        __syncthreads();
    }
    int run = ssum[t] - s;
    for (int i = beg; i < end; i++) {
        g_offsets[i] = run;
        g_cursor[i]  = run;
        run += g_counts[i];
    }
    if (t == 1023) g_offsets[n] = run;
}

__global__ void scatter_edges(const void* ei, const float* w, long E) {
    long e = blockIdx.x * (long)blockDim.x + threadIdx.x;
    if (e >= E) return;
    long src = ld_idx(ei, e);
    long dst = ld_idx(ei, E + e);
    float nw = g_dinv[src] * w[e] * g_dinv[dst];
    int pos = atomicAdd(&g_cursor[(int)dst], 1);
    g_epack[pos] = make_uint2((unsigned)src, __float_as_uint(nw));
}

// ---------------- fp32 -> bf16 hi/lo split ----------------
__device__ __forceinline__ unsigned pk(BF16 lo, BF16 hi) {
    __nv_bfloat162 t = __halves2bfloat162(lo, hi);
    return *reinterpret_cast<unsigned*>(&t);
}

__global__ void convert_split(const float* __restrict__ in,
                              BF16* __restrict__ hi, BF16* __restrict__ lo,
                              long n4) {
    long i = blockIdx.x * (long)blockDim.x + threadIdx.x;
    if (i >= n4) return;
    float4 v = ((const float4*)in)[i];
    BF16 h0 = __float2bfloat16_rn(v.x), h1 = __float2bfloat16_rn(v.y);
    BF16 h2 = __float2bfloat16_rn(v.z), h3 = __float2bfloat16_rn(v.w);
    BF16 l0 = __float2bfloat16_rn(v.x - __bfloat162float(h0));
    BF16 l1 = __float2bfloat16_rn(v.y - __bfloat162float(h1));
    BF16 l2 = __float2bfloat16_rn(v.z - __bfloat162float(h2));
    BF16 l3 = __float2bfloat16_rn(v.w - __bfloat162float(h3));
    ((uint2*)hi)[i] = make_uint2(pk(h0, h1), pk(h2, h3));
    ((uint2*)lo)[i] = make_uint2(pk(l0, l1), pk(l2, l3));
}

// ---------------- mma helpers ----------------
__device__ __forceinline__ uint32_t s2u(const void* p) {
    return (uint32_t)__cvta_generic_to_shared(p);
}

__device__ __forceinline__ void ldsm_x4(unsigned* r, const void* p) {
    unsigned a = (unsigned)__cvta_generic_to_shared(p);
    asm volatile("ldmatrix.sync.aligned.m8n8.x4.shared.b16 {%0,%1,%2,%3}, [%4];"
                 : "=r"(r[0]), "=r"(r[1]), "=r"(r[2]), "=r"(r[3]) : "r"(a));
}

__device__ __forceinline__ void ldsm_x4_t(unsigned* r, const void* p) {
    unsigned a = (unsigned)__cvta_generic_to_shared(p);
    asm volatile("ldmatrix.sync.aligned.m8n8.x4.trans.shared.b16 {%0,%1,%2,%3}, [%4];"
                 : "=r"(r[0]), "=r"(r[1]), "=r"(r[2]), "=r"(r[3]) : "r"(a));
}

__device__ __forceinline__ void mma_bf16(float* d, const unsigned* a, const unsigned* b) {
    asm volatile(
        "mma.sync.aligned.m16n8k16.row.col.f32.bf16.bf16.f32 "
        "{%0,%1,%2,%3}, {%4,%5,%6,%7}, {%8,%9}, {%0,%1,%2,%3};"
        : "+f"(d[0]), "+f"(d[1]), "+f"(d[2]), "+f"(d[3])
        : "r"(a[0]), "r"(a[1]), "r"(a[2]), "r"(a[3]), "r"(b[0]), "r"(b[1]));
}

__device__ __forceinline__ void cpa16(uint32_t dst, const void* src, int srcbytes) {
    asm volatile("cp.async.cg.shared.global [%0], [%1], 16, %2;"
                 :: "r"(dst), "l"(src), "r"(srcbytes));
}

#define CP_COMMIT() asm volatile("cp.async.commit_group;" ::: "memory")
#define CP_WAIT1()  asm volatile("cp.async.wait_group 1;" ::: "memory")

// ---------------- cp.async 3-stage tensor-core GEMM (bf16x3) ----------------
// C[M,N] = (Ah+Al)[M,K] @ (Bh+Bl)[K,N], writes H.
// Block tile 64x128x32, 256 threads (8 warps, 2x4 grid, 32x32 warp tiles),
// 3 stages, 2 CTAs/SM (barrier bubbles overlap across CTAs).
// Stage layout (bytes): Ah@0 (5120), Al@5120, Bh@10240 (8704), Bl@18944.
#define STAGE_BYTES 27648
#define GEMM_DSMEM  (3 * STAGE_BYTES)

__global__ __launch_bounds__(256, 2) void gemm_bf16x3(
    int M, int N, int K,
    const BF16* __restrict__ AH, const BF16* __restrict__ AL,
    const BF16* __restrict__ BH, const BF16* __restrict__ BL,
    float* __restrict__ H)
{
    extern __shared__ __align__(16) char dynsm[];
    const int tid = threadIdx.x, lane = tid & 31, warp = tid >> 5;
    const int wm = warp >> 2, wn = warp & 3;       // 2 x 4 warp grid
    const int bRow = blockIdx.x, bCol = blockIdx.y;
    const int nk = K / 32;

    // cp.async coords: A 64 rows x 4 chunks(16B) = 256 -> 1 chunk/thread
    const int ar = tid >> 2;            // 0..63
    const int ac = tid & 3;             // 0..3
    // B 32 rows x 16 chunks = 512 -> 2 chunks/thread
    const int br  = tid >> 3;           // 0..31
    const int bc0 = (tid & 7) * 2;      // 0..14

    const int gra  = bRow * 64 + ar;
    const int grac = min(gra, M - 1);
    const int asz  = (gra < M) ? 16 : 0;
    const char* gA  = (const char*)(AH + (size_t)grac * K);
    const char* gAl = (const char*)(AL + (size_t)grac * K);
    const char* gB  = (const char*)(BH + (size_t)br * N + bCol * 128);
    const char* gBl = (const char*)(BL + (size_t)br * N + bCol * 128);

    auto issue = [&](int kb, int s) {
        char* base = dynsm + s * STAGE_BYTES;
        cpa16(s2u(base + ar * 80) + ac * 16,        gA  + (size_t)kb * 64 + ac * 16, asz);
        cpa16(s2u(base + 5120 + ar * 80) + ac * 16, gAl + (size_t)kb * 64 + ac * 16, asz);
        const char* pb  = gB  + (size_t)kb * 32 * N * 2;
        const char* pbl = gBl + (size_t)kb * 32 * N * 2;
        uint32_t sb  = s2u(base + 10240 + br * 272);
        uint32_t sbl = s2u(base + 18944 + br * 272);
        cpa16(sb  + bc0 * 16,       pb  + bc0 * 16,       16);
        cpa16(sb  + (bc0 + 1) * 16, pb  + (bc0 + 1) * 16, 16);
        cpa16(sbl + bc0 * 16,       pbl + bc0 * 16,       16);
        cpa16(sbl + (bc0 + 1) * 16, pbl + (bc0 + 1) * 16, 16);
    };

    float acc[2][4][4];
#pragma unroll
    for (int mi = 0; mi < 2; mi++)
#pragma unroll
        for (int nj = 0; nj < 4; nj++)
#pragma unroll
            for (int r = 0; r < 4; r++) acc[mi][nj][r] = 0.f;

    issue(0, 0); CP_COMMIT();
    if (nk > 1) issue(1, 1);
    CP_COMMIT();

    const int g8  = lane & 7;
    const int m01 = (lane >> 3) & 1;
    const int m23 = lane >> 4;

    for (int kb = 0; kb < nk; kb++) {
        const int s = kb % 3;
        CP_WAIT1();
        __syncthreads();

        unsigned short* Ahp = (unsigned short*)(dynsm + s * STAGE_BYTES);
        unsigned short* Alp = (unsigned short*)(dynsm + s * STAGE_BYTES + 5120);
        unsigned short* Bhp = (unsigned short*)(dynsm + s * STAGE_BYTES + 10240);
        unsigned short* Blp = (unsigned short*)(dynsm + s * STAGE_BYTES + 18944);

#pragma unroll
        for (int kk = 0; kk < 2; kk++) {
            const int k0 = kk * 16;
            unsigned aFh[2][4], aFl[2][4], bFh[4][2], bFl[4][2];
#pragma unroll
            for (int mi = 0; mi < 2; mi++) {
                int row = wm * 32 + mi * 16 + g8 + m01 * 8;
                int kof = k0 + m23 * 8;
                ldsm_x4(aFh[mi], &Ahp[row * 40 + kof]);
                ldsm_x4(aFl[mi], &Alp[row * 40 + kof]);
            }
#pragma unroll
            for (int bj = 0; bj < 2; bj++) {
                int krow = k0 + g8 + m01 * 8;
                int ncol = wn * 32 + bj * 16 + m23 * 8;
                unsigned t[4];
                ldsm_x4_t(t, &Bhp[krow * 136 + ncol]);
                bFh[2 * bj][0] = t[0]; bFh[2 * bj][1] = t[1];
                bFh[2 * bj + 1][0] = t[2]; bFh[2 * bj + 1][1] = t[3];
                ldsm_x4_t(t, &Blp[krow * 136 + ncol]);
                bFl[2 * bj][0] = t[0]; bFl[2 * bj][1] = t[1];
                bFl[2 * bj + 1][0] = t[2]; bFl[2 * bj + 1][1] = t[3];
            }
#pragma unroll
            for (int mi = 0; mi < 2; mi++)
#pragma unroll
                for (int nj = 0; nj < 4; nj++) {
                    mma_bf16(acc[mi][nj], aFh[mi], bFh[nj]);
                    mma_bf16(acc[mi][nj], aFh[mi], bFl[nj]);
                    mma_bf16(acc[mi][nj], aFl[mi], bFh[nj]);
                }
        }

        int nkb = kb + 2;
        if (nkb < nk) issue(nkb, nkb % 3);
        CP_COMMIT();
    }

    const int gg = lane >> 2, cc = lane & 3;
#pragma unroll
    for (int mi = 0; mi < 2; mi++) {
        int rb = bRow * 64 + wm * 32 + mi * 16;
        int r0 = rb + gg, r1 = rb + gg + 8;
#pragma unroll
        for (int nj = 0; nj < 4; nj++) {
            int col = bCol * 128 + wn * 32 + nj * 8 + 2 * cc;
            float* a = acc[mi][nj];
            if (r0 < M) *(float2*)(H + (size_t)r0 * N + col) = make_float2(a[0], a[1]);
            if (r1 < M) *(float2*)(H + (size_t)r1 * N + col) = make_float2(a[2], a[3]);
        }
    }
}

// ---------------- CSR gather aggregation (atomic-free, 2-edge unrolled) ----------------
template <int MODE>
__global__ __launch_bounds__(256) void gather_agg(
    const float* __restrict__ h, const float* __restrict__ bias,
    float* __restrict__ AGGF, BF16* __restrict__ AHo, BF16* __restrict__ ALo,
    int M)
{
    int warp = (blockIdx.x * blockDim.x + threadIdx.x) >> 5;
    int lane = threadIdx.x & 31;
    if (warp >= M) return;
    int dst = warp;
    int beg = g_offsets[dst], end = g_offsets[dst + 1];

    float4 s0a = make_float4(0.f, 0.f, 0.f, 0.f);
    float4 s0b = make_float4(0.f, 0.f, 0.f, 0.f);
    float4 s1a = make_float4(0.f, 0.f, 0.f, 0.f);
    float4 s1b = make_float4(0.f, 0.f, 0.f, 0.f);

    int e = beg;
    for (; e + 2 <= end; e += 2) {
        uint2 p0 = g_epack[e];
        uint2 p1 = g_epack[e + 1];
        float w0 = __uint_as_float(p0.y);
        float w1 = __uint_as_float(p1.y);
        const float4* q0 = (const float4*)(h + (size_t)p0.x * F);
        const float4* q1 = (const float4*)(h + (size_t)p1.x * F);
        float4 u00 = q0[lane], u01 = q0[lane + 32];
        float4 u10 = q1[lane], u11 = q1[lane + 32];
        s0a.x += w0 * u00.x; s0a.y += w0 * u00.y; s0a.z += w0 * u00.z; s0a.w += w0 * u00.w;
        s0b.x += w0 * u01.x; s0b.y += w0 * u01.y; s0b.z += w0 * u01.z; s0b.w += w0 * u01.w;
        s1a.x += w1 * u10.x; s1a.y += w1 * u10.y; s1a.z += w1 * u10.z; s1a.w += w1 * u10.w;
        s1b.x += w1 * u11.x; s1b.y += w1 * u11.y; s1b.z += w1 * u11.z; s1b.w += w1 * u11.w;
    }
    if (e < end) {
        uint2 p0 = g_epack[e];
        float w0 = __uint_as_float(p0.y);
        const float4* q0 = (const float4*)(h + (size_t)p0.x * F);
        float4 u00 = q0[lane], u01 = q0[lane + 32];
        s0a.x += w0 * u00.x; s0a.y += w0 * u00.y; s0a.z += w0 * u00.z; s0a.w += w0 * u00.w;
        s0b.x += w0 * u01.x; s0b.y += w0 * u01.y; s0b.z += w0 * u01.z; s0b.w += w0 * u01.w;
    }

    float di = g_dinv[dst], s = di * di;
    const float4* hd = (const float4*)(h + (size_t)dst * F);
    const float4* bp = (const float4*)bias;
    float4 u0 = hd[lane], u1 = hd[lane + 32];
    float4 b0 = bp[lane], b1 = bp[lane + 32];
    float4 o0, o1;
    o0.x = fmaxf(b0.x + s * u0.x + s0a.x + s1a.x, 0.f);
    o0.y = fmaxf(b0.y + s * u0.y + s0a.y + s1a.y, 0.f);
    o0.z = fmaxf(b0.z + s * u0.z + s0a.z + s1a.z, 0.f);
    o0.w = fmaxf(b0.w + s * u0.w + s0a.w + s1a.w, 0.f);
    o1.x = fmaxf(b1.x + s * u1.x + s0b.x + s1b.x, 0.f);
    o1.y = fmaxf(b1.y + s * u1.y + s0b.y + s1b.y, 0.f);
    o1.z = fmaxf(b1.z + s * u1.z + s0b.z + s1b.z, 0.f);
    o1.w = fmaxf(b1.w + s * u1.w + s0b.w + s1b.w, 0.f);

    if (MODE == 0) {
        float4* ap = (float4*)(AGGF + (size_t)dst * F);
        ap[lane] = o0;
        ap[lane + 32] = o1;
    } else {
        BF16 h0 = __float2bfloat16_rn(o0.x), h1 = __float2bfloat16_rn(o0.y);
        BF16 h2 = __float2bfloat16_rn(o0.z), h3 = __float2bfloat16_rn(o0.w);
        BF16 l0 = __float2bfloat16_rn(o0.x - __bfloat162float(h0));
        BF16 l1 = __float2bfloat16_rn(o0.y - __bfloat162float(h1));
        BF16 l2 = __float2bfloat16_rn(o0.z - __bfloat162float(h2));
        BF16 l3 = __float2bfloat16_rn(o0.w - __bfloat162float(h3));
        BF16 h4 = __float2bfloat16_rn(o1.x), h5 = __float2bfloat16_rn(o1.y);
        BF16 h6 = __float2bfloat16_rn(o1.z), h7 = __float2bfloat16_rn(o1.w);
        BF16 l4 = __float2bfloat16_rn(o1.x - __bfloat162float(h4));
        BF16 l5 = __float2bfloat16_rn(o1.y - __bfloat162float(h5));
        BF16 l6 = __float2bfloat16_rn(o1.z - __bfloat162float(h6));
        BF16 l7 = __float2bfloat16_rn(o1.w - __bfloat162float(h7));
        uint2* ph = (uint2*)(AHo + (size_t)dst * F);
        uint2* pl = (uint2*)(ALo + (size_t)dst * F);
        ph[lane]      = make_uint2(pk(h0, h1), pk(h2, h3));
        ph[lane + 32] = make_uint2(pk(h4, h5), pk(h6, h7));
        pl[lane]      = make_uint2(pk(l0, l1), pk(l2, l3));
        pl[lane + 32] = make_uint2(pk(l4, l5), pk(l6, l7));
    }
}

// ---------------- BN stats over agg2 (already relu'd) ----------------
__global__ void bn_zero() {
    int f = threadIdx.x;
    g_bnsum[f] = 0.0f;
    g_bnssq[f] = 0.0f;
}

__global__ void bn_stats(const float* __restrict__ agg2, int M, int rows_per_block) {
    int f = threadIdx.x;
    long r0 = blockIdx.x * (long)rows_per_block;
    long r1 = r0 + rows_per_block; if (r1 > M) r1 = M;
    float s = 0.f, ss = 0.f;
    for (long r = r0; r < r1; r++) {
        float v = agg2[r * F + f];
        s += v; ss += v * v;
    }
    atomicAdd(&g_bnsum[f], s);
    atomicAdd(&g_bnssq[f], ss);
}

// ---------------- fused BN + LN ----------------
__global__ void bn_ln_final(const float* __restrict__ agg2,
                            const float* __restrict__ bg, const float* __restrict__ bb,
                            const float* __restrict__ lg, const float* __restrict__ lb,
                            float* __restrict__ out, int M) {
    long r = blockIdx.x;
    int  f = threadIdx.x;
    int  lane = f & 31, wid = f >> 5;
    float invM = 1.0f / (float)M;

    float mu  = g_bnsum[f] * invM;
    float var = g_bnssq[f] * invM - mu * mu;
    float v = agg2[r * F + f];
    float y = (v - mu) * rsqrtf(var + EPSV) * bg[f] + bb[f];

    float s = y, ss = y * y;
#pragma unroll
    for (int o = 16; o > 0; o >>= 1) {
        s  += __shfl_xor_sync(0xffffffffu, s,  o);
        ss += __shfl_xor_sync(0xffffffffu, ss, o);
    }
    __shared__ float reds[8], redss[8];
    if (lane == 0) { reds[wid] = s; redss[wid] = ss; }
    __syncthreads();
    if (wid == 0) {
        float a = lane < 8 ? reds[lane]  : 0.f;
        float b = lane < 8 ? redss[lane] : 0.f;
#pragma unroll
        for (int o = 4; o > 0; o >>= 1) {
            a += __shfl_xor_sync(0xffffffffu, a, o);
            b += __shfl_xor_sync(0xffffffffu, b, o);
        }
        if (lane == 0) { reds[0] = a; redss[0] = b; }
    }
    __syncthreads();
    float lmu  = reds[0]  * (1.0f / F);
    float lvar = redss[0] * (1.0f / F) - lmu * lmu;
    out[r * F + f] = (y - lmu) * rsqrtf(lvar + EPSV) * lg[f] + lb[f];
}

// ---------------- launcher ----------------
extern "C" void kernel_launch(void* const* d_in, const int* in_sizes, int n_in,
                              void* d_out, int out_size) {
    const float* x  = (const float*)d_in[0];
    const void*  ei = d_in[1];
    const float* ew = (const float*)d_in[2];
    const float* W1 = (const float*)d_in[3];
    const float* b1 = (const float*)d_in[4];
    const float* W2 = (const float*)d_in[5];
    const float* b2 = (const float*)d_in[6];
    const float* bg = (const float*)d_in[7];
    const float* bb = (const float*)d_in[8];
    const float* lg = (const float*)d_in[9];
    const float* lb = (const float*)d_in[10];
    float* out = (float*)d_out;

    int  n = in_sizes[0] / NFEAT;            // 50000
    long E = in_sizes[1] / 2;                // 800000
    if (E > E_MAX) E = E_MAX;

    float* h1;   cudaGetSymbolAddress((void**)&h1,   g_h1);
    float* h2;   cudaGetSymbolAddress((void**)&h2,   g_h2);
    float* agg2; cudaGetSymbolAddress((void**)&agg2, g_agg2);
    BF16 *xh, *xl, *a1h, *a1l, *w1h, *w1l, *w2h, *w2l;
    cudaGetSymbolAddress((void**)&xh,  g_xh);
    cudaGetSymbolAddress((void**)&xl,  g_xl);
    cudaGetSymbolAddress((void**)&a1h, g_a1h);
    cudaGetSymbolAddress((void**)&a1l, g_a1l);
    cudaGetSymbolAddress((void**)&w1h, g_w1h);
    cudaGetSymbolAddress((void**)&w1l, g_w1l);
    cudaGetSymbolAddress((void**)&w2h, g_w2h);
    cudaGetSymbolAddress((void**)&w2l, g_w2l);

    cudaFuncSetAttribute(gemm_bf16x3,
                         cudaFuncAttributeMaxDynamicSharedMemorySize, GEMM_DSMEM);

    int eb = (int)((E + 255) / 256);
    long x4  = (long)n * NFEAT / 4;
    long w14 = (long)NFEAT * F / 4;
    long w24 = (long)F * F / 4;
    dim3 gg((n + 63) / 64, F / 128);
    int gatherBlocks = (n * 32 + 255) / 256;

    // ---- launches 0-2: converts (gemm1 prereqs) ----
    convert_split<<<(int)((x4 + 255) / 256), 256>>>(x,  xh,  xl,  x4);
    convert_split<<<(int)((w14 + 255) / 256), 256>>>(W1, w1h, w1l, w14);
    convert_split<<<(int)((w24 + 255) / 256), 256>>>(W2, w2h, w2l, w24);

    // ---- launch 3: GEMM1 (positioned at the ncu capture slot) ----
    gemm_bf16x3<<<gg, 256, GEMM_DSMEM>>>(n, F, NFEAT, xh, xl, w1h, w1l, h1);

    // ---- CSR + degree chain (independent of GEMM1) ----
    detect_idx_dtype<<<1, 256>>>((const int*)ei, 1024);
    zero_counts_deg<<<(n + 255) / 256, 256>>>(n);
    histo_deg<<<eb, 256>>>(ei, ew, E);
    compute_dinv<<<(n + 255) / 256, 256>>>(n);
    scan_offsets<<<1, 1024>>>(n);
    scatter_edges<<<eb, 256>>>(ei, ew, E);

    // ---- layer 1 aggregation (writes relu-split bf16 directly) ----
    gather_agg<1><<<gatherBlocks, 256>>>(h1, b1, nullptr, a1h, a1l, n);

    // ---- layer 2 ----
    gemm_bf16x3<<<gg, 256, GEMM_DSMEM>>>(n, F, F, a1h, a1l, w2h, w2l, h2);
    gather_agg<0><<<gatherBlocks, 256>>>(h2, b2, agg2, nullptr, nullptr, n);

    // ---- BN stats + fused BN/LN ----
    bn_zero<<<1, F>>>();
    const int RPB = 128;
    bn_stats<<<(n + RPB - 1) / RPB, F>>>(agg2, n, RPB);
    bn_ln_final<<<n, F>>>(agg2, bg, bb, lg, lb, out, n);
}

// round 12
// speedup vs baseline: 2.1704x; 1.0565x over previous
#include <cuda_runtime.h>
#include <cuda_bf16.h>
#include <stdint.h>

#define N_NODES 50000
#define F 256
#define NFEAT 1024
#define E_MAX 800000
#define EPSV 1e-5f
typedef __nv_bfloat16 BF16;

// ---------------- scratch (__device__ globals) ----------------
__device__ float g_h1  [(size_t)N_NODES * F];
__device__ float g_h2  [(size_t)N_NODES * F];
__device__ float g_agg2[(size_t)N_NODES * F];
__device__ BF16 g_xh[(size_t)N_NODES * NFEAT];
__device__ BF16 g_xl[(size_t)N_NODES * NFEAT];
__device__ BF16 g_a1h[(size_t)N_NODES * F];
__device__ BF16 g_a1l[(size_t)N_NODES * F];
__device__ BF16 g_w1h[NFEAT * F], g_w1l[NFEAT * F];
__device__ BF16 g_w2h[F * F],     g_w2l[F * F];
__device__ float g_deg [N_NODES];
__device__ float g_dinv[N_NODES];
__device__ int   g_counts [N_NODES];
__device__ int   g_offsets[N_NODES + 1];
__device__ int   g_cursor [N_NODES];
__device__ uint2 g_epack  [E_MAX];          // (src, norm-weight)
__device__ float g_bnsum[F];
__device__ float g_bnssq[F];
__device__ int   g_is64;

// ---------------- edge_index dtype detection ----------------
__global__ void detect_idx_dtype(const int* ei32, int n_check) {
    __shared__ int bad;
    if (threadIdx.x == 0) bad = 0;
    __syncthreads();
    for (int i = threadIdx.x; i < n_check; i += blockDim.x)
        if (ei32[2 * i + 1] != 0) bad = 1;
    __syncthreads();
    if (threadIdx.x == 0) g_is64 = bad ? 0 : 1;
}

__device__ __forceinline__ long ld_idx(const void* ei, long i) {
    return g_is64 ? (long)((const long long*)ei)[i] : (long)((const int*)ei)[i];
}

// ---------------- degree + CSR ----------------
__global__ void zero_counts_deg(int n) {
    int i = blockIdx.x * blockDim.x + threadIdx.x;
    if (i < n) { g_counts[i] = 0; g_deg[i] = 1.0f; }
}

__global__ void histo_deg(const void* ei, const float* w, long E) {
    long e = blockIdx.x * (long)blockDim.x + threadIdx.x;
    if (e >= E) return;
    long dst = ld_idx(ei, E + e);
    atomicAdd(&g_deg[dst], w[e]);
    atomicAdd(&g_counts[(int)dst], 1);
}

__global__ void compute_dinv(int n) {
    int i = blockIdx.x * blockDim.x + threadIdx.x;
    if (i < n) {
        float d = g_deg[i];
        g_dinv[i] = d > 0.0f ? rsqrtf(fmaxf(d, 1e-30f)) : 0.0f;
    }
}

__global__ __launch_bounds__(1024) void scan_offsets(int n) {
    __shared__ int ssum[1024];
    int t = threadIdx.x;
    int chunk = (n + 1023) / 1024;
    int beg = t * chunk, end = min(beg + chunk, n);
    int s = 0;
    for (int i = beg; i < end; i++) s += g_counts[i];
    ssum[t] = s;
    __syncthreads();
    for (int o = 1; o < 1024; o <<= 1) {
        int u = (t >= o) ? ssum[t - o] : 0;
        __syncthreads();
        ssum[t] += u;
        __syncthreads();
    }
    int run = ssum[t] - s;
    for (int i = beg; i < end; i++) {
        g_offsets[i] = run;
        g_cursor[i]  = run;
        run += g_counts[i];
    }
    if (t == 1023) g_offsets[n] = run;
}

__global__ void scatter_edges(const void* ei, const float* w, long E) {
    long e = blockIdx.x * (long)blockDim.x + threadIdx.x;
    if (e >= E) return;
    long src = ld_idx(ei, e);
    long dst = ld_idx(ei, E + e);
    float nw = g_dinv[src] * w[e] * g_dinv[dst];
    int pos = atomicAdd(&g_cursor[(int)dst], 1);
    g_epack[pos] = make_uint2((unsigned)src, __float_as_uint(nw));
}

// ---------------- fp32 -> bf16 hi/lo split ----------------
__device__ __forceinline__ unsigned pk(BF16 lo, BF16 hi) {
    __nv_bfloat162 t = __halves2bfloat162(lo, hi);
    return *reinterpret_cast<unsigned*>(&t);
}

__global__ void convert_split(const float* __restrict__ in,
                              BF16* __restrict__ hi, BF16* __restrict__ lo,
                              long n4) {
    long i = blockIdx.x * (long)blockDim.x + threadIdx.x;
    if (i >= n4) return;
    float4 v = ((const float4*)in)[i];
    BF16 h0 = __float2bfloat16_rn(v.x), h1 = __float2bfloat16_rn(v.y);
    BF16 h2 = __float2bfloat16_rn(v.z), h3 = __float2bfloat16_rn(v.w);
    BF16 l0 = __float2bfloat16_rn(v.x - __bfloat162float(h0));
    BF16 l1 = __float2bfloat16_rn(v.y - __bfloat162float(h1));
    BF16 l2 = __float2bfloat16_rn(v.z - __bfloat162float(h2));
    BF16 l3 = __float2bfloat16_rn(v.w - __bfloat162float(h3));
    ((uint2*)hi)[i] = make_uint2(pk(h0, h1), pk(h2, h3));
    ((uint2*)lo)[i] = make_uint2(pk(l0, l1), pk(l2, l3));
}

// ---------------- mma helpers ----------------
__device__ __forceinline__ uint32_t s2u(const void* p) {
    return (uint32_t)__cvta_generic_to_shared(p);
}

__device__ __forceinline__ void ldsm_x4(unsigned* r, const void* p) {
    unsigned a = (unsigned)__cvta_generic_to_shared(p);
    asm volatile("ldmatrix.sync.aligned.m8n8.x4.shared.b16 {%0,%1,%2,%3}, [%4];"
                 : "=r"(r[0]), "=r"(r[1]), "=r"(r[2]), "=r"(r[3]) : "r"(a));
}

__device__ __forceinline__ void ldsm_x4_t(unsigned* r, const void* p) {
    unsigned a = (unsigned)__cvta_generic_to_shared(p);
    asm volatile("ldmatrix.sync.aligned.m8n8.x4.trans.shared.b16 {%0,%1,%2,%3}, [%4];"
                 : "=r"(r[0]), "=r"(r[1]), "=r"(r[2]), "=r"(r[3]) : "r"(a));
}

__device__ __forceinline__ void mma_bf16(float* d, const unsigned* a, const unsigned* b) {
    asm volatile(
        "mma.sync.aligned.m16n8k16.row.col.f32.bf16.bf16.f32 "
        "{%0,%1,%2,%3}, {%4,%5,%6,%7}, {%8,%9}, {%0,%1,%2,%3};"
        : "+f"(d[0]), "+f"(d[1]), "+f"(d[2]), "+f"(d[3])
        : "r"(a[0]), "r"(a[1]), "r"(a[2]), "r"(a[3]), "r"(b[0]), "r"(b[1]));
}

__device__ __forceinline__ void cpa16(uint32_t dst, const void* src, int srcbytes) {
    asm volatile("cp.async.cg.shared.global [%0], [%1], 16, %2;"
                 :: "r"(dst), "l"(src), "r"(srcbytes));
}

#define CP_COMMIT() asm volatile("cp.async.commit_group;" ::: "memory")
#define CP_WAIT1()  asm volatile("cp.async.wait_group 1;" ::: "memory")

// ---------------- cp.async 3-stage tensor-core GEMM (bf16x3) ----------------
// C[M,N] = (Ah+Al)[M,K] @ (Bh+Bl)[K,N], writes H.
// Block tile 128x128x32, 256 threads, warp grid 2x4 with 64x32 warp tiles
// (168 B smem per MMA vs 229 at 32x32 -> smem-BW headroom), 3 stages,
// 2 CTAs/SM forced by launch_bounds (227 KB smem total).
// Stage layout (bytes): Ah@0 (10240), Al@10240, Bh@20480 (8704), Bl@29184.
#define STAGE_BYTES 37888
#define GEMM_DSMEM  (3 * STAGE_BYTES)

__global__ __launch_bounds__(256, 2) void gemm_bf16x3(
    int M, int N, int K,
    const BF16* __restrict__ AH, const BF16* __restrict__ AL,
    const BF16* __restrict__ BH, const BF16* __restrict__ BL,
    float* __restrict__ H)
{
    extern __shared__ __align__(16) char dynsm[];
    const int tid = threadIdx.x, lane = tid & 31, warp = tid >> 5;
    const int wm = warp >> 2, wn = warp & 3;       // 2 x 4 warp grid, 64x32 tiles
    const int bRow = blockIdx.x, bCol = blockIdx.y;
    const int nk = K / 32;

    // cp.async coords: A 128 rows x 4 chunks(16B) x2 arrays -> 2 chunks/thread/array
    const int ar  = tid >> 1;           // 0..127
    const int ac0 = (tid & 1) * 2;      // 0 or 2
    // B 32 rows x 16 chunks x2 arrays -> 2 chunks/thread/array
    const int br  = tid >> 3;           // 0..31
    const int bc0 = (tid & 7) * 2;      // 0..14

    const int gra  = bRow * 128 + ar;
    const int grac = min(gra, M - 1);
    const int asz  = (gra < M) ? 16 : 0;
    const char* gA  = (const char*)(AH + (size_t)grac * K);
    const char* gAl = (const char*)(AL + (size_t)grac * K);
    const char* gB  = (const char*)(BH + (size_t)br * N + bCol * 128);
    const char* gBl = (const char*)(BL + (size_t)br * N + bCol * 128);

    auto issue = [&](int kb, int s) {
        char* base = dynsm + s * STAGE_BYTES;
        const char* pa  = gA  + (size_t)kb * 64;
        const char* pal = gAl + (size_t)kb * 64;
        uint32_t sa  = s2u(base + ar * 80);
        uint32_t sal = s2u(base + 10240 + ar * 80);
        cpa16(sa  + ac0 * 16,       pa  + ac0 * 16,       asz);
        cpa16(sa  + (ac0 + 1) * 16, pa  + (ac0 + 1) * 16, asz);
        cpa16(sal + ac0 * 16,       pal + ac0 * 16,       asz);
        cpa16(sal + (ac0 + 1) * 16, pal + (ac0 + 1) * 16, asz);
        const char* pb  = gB  + (size_t)kb * 32 * N * 2;
        const char* pbl = gBl + (size_t)kb * 32 * N * 2;
        uint32_t sb  = s2u(base + 20480 + br * 272);
        uint32_t sbl = s2u(base + 29184 + br * 272);
        cpa16(sb  + bc0 * 16,       pb  + bc0 * 16,       16);
        cpa16(sb  + (bc0 + 1) * 16, pb  + (bc0 + 1) * 16, 16);
        cpa16(sbl + bc0 * 16,       pbl + bc0 * 16,       16);
        cpa16(sbl + (bc0 + 1) * 16, pbl + (bc0 + 1) * 16, 16);
    };

    float acc[4][4][4];
#pragma unroll
    for (int mi = 0; mi < 4; mi++)
#pragma unroll
        for (int nj = 0; nj < 4; nj++)
#pragma unroll
            for (int r = 0; r < 4; r++) acc[mi][nj][r] = 0.f;

    issue(0, 0); CP_COMMIT();
    if (nk > 1) issue(1, 1);
    CP_COMMIT();

    const int g8  = lane & 7;
    const int m01 = (lane >> 3) & 1;
    const int m23 = lane >> 4;

    for (int kb = 0; kb < nk; kb++) {
        const int s = kb % 3;
        CP_WAIT1();
        __syncthreads();

        unsigned short* Ahp = (unsigned short*)(dynsm + s * STAGE_BYTES);
        unsigned short* Alp = (unsigned short*)(dynsm + s * STAGE_BYTES + 10240);
        unsigned short* Bhp = (unsigned short*)(dynsm + s * STAGE_BYTES + 20480);
        unsigned short* Blp = (unsigned short*)(dynsm + s * STAGE_BYTES + 29184);

#pragma unroll
        for (int kk = 0; kk < 2; kk++) {
            const int k0 = kk * 16;
            // A frags for 64 rows (mi 0..3), hi+lo
            unsigned aFh[4][4], aFl[4][4];
#pragma unroll
            for (int mi = 0; mi < 4; mi++) {
                int row = wm * 64 + mi * 16 + g8 + m01 * 8;
                int kof = k0 + m23 * 8;
                ldsm_x4(aFh[mi], &Ahp[row * 40 + kof]);
                ldsm_x4(aFl[mi], &Alp[row * 40 + kof]);
            }
            // B frags per nj-pair, kept live only within the bj iteration
#pragma unroll
            for (int bj = 0; bj < 2; bj++) {
                int krow = k0 + g8 + m01 * 8;
                int ncol = wn * 32 + bj * 16 + m23 * 8;
                unsigned bFh[2][2], bFl[2][2];
                unsigned t[4];
                ldsm_x4_t(t, &Bhp[krow * 136 + ncol]);
                bFh[0][0] = t[0]; bFh[0][1] = t[1];
                bFh[1][0] = t[2]; bFh[1][1] = t[3];
                ldsm_x4_t(t, &Blp[krow * 136 + ncol]);
                bFl[0][0] = t[0]; bFl[0][1] = t[1];
                bFl[1][0] = t[2]; bFl[1][1] = t[3];
#pragma unroll
                for (int mi = 0; mi < 4; mi++)
#pragma unroll
                    for (int q = 0; q < 2; q++) {
                        int nj = 2 * bj + q;
                        mma_bf16(acc[mi][nj], aFh[mi], bFh[q]);
                        mma_bf16(acc[mi][nj], aFh[mi], bFl[q]);
                        mma_bf16(acc[mi][nj], aFl[mi], bFh[q]);
                    }
            }
        }

        int nkb = kb + 2;
        if (nkb < nk) issue(nkb, nkb % 3);
        CP_COMMIT();
    }

    const int gg = lane >> 2, cc = lane & 3;
#pragma unroll
    for (int mi = 0; mi < 4; mi++) {
        int rb = bRow * 128 + wm * 64 + mi * 16;
        int r0 = rb + gg, r1 = rb + gg + 8;
#pragma unroll
        for (int nj = 0; nj < 4; nj++) {
            int col = bCol * 128 + wn * 32 + nj * 8 + 2 * cc;
            float* a = acc[mi][nj];
            if (r0 < M) *(float2*)(H + (size_t)r0 * N + col) = make_float2(a[0], a[1]);
            if (r1 < M) *(float2*)(H + (size_t)r1 * N + col) = make_float2(a[2], a[3]);
        }
    }
}

// ---------------- CSR gather aggregation (atomic-free, 2-edge unrolled) ----------------
template <int MODE>
__global__ __launch_bounds__(256) void gather_agg(
    const float* __restrict__ h, const float* __restrict__ bias,
    float* __restrict__ AGGF, BF16* __restrict__ AHo, BF16* __restrict__ ALo,
    int M)
{
    int warp = (blockIdx.x * blockDim.x + threadIdx.x) >> 5;
    int lane = threadIdx.x & 31;
    if (warp >= M) return;
    int dst = warp;
    int beg = g_offsets[dst], end = g_offsets[dst + 1];

    float4 s0a = make_float4(0.f, 0.f, 0.f, 0.f);
    float4 s0b = make_float4(0.f, 0.f, 0.f, 0.f);
    float4 s1a = make_float4(0.f, 0.f, 0.f, 0.f);
    float4 s1b = make_float4(0.f, 0.f, 0.f, 0.f);

    int e = beg;
    for (; e + 2 <= end; e += 2) {
        uint2 p0 = g_epack[e];
        uint2 p1 = g_epack[e + 1];
        float w0 = __uint_as_float(p0.y);
        float w1 = __uint_as_float(p1.y);
        const float4* q0 = (const float4*)(h + (size_t)p0.x * F);
        const float4* q1 = (const float4*)(h + (size_t)p1.x * F);
        float4 u00 = q0[lane], u01 = q0[lane + 32];
        float4 u10 = q1[lane], u11 = q1[lane + 32];
        s0a.x += w0 * u00.x; s0a.y += w0 * u00.y; s0a.z += w0 * u00.z; s0a.w += w0 * u00.w;
        s0b.x += w0 * u01.x; s0b.y += w0 * u01.y; s0b.z += w0 * u01.z; s0b.w += w0 * u01.w;
        s1a.x += w1 * u10.x; s1a.y += w1 * u10.y; s1a.z += w1 * u10.z; s1a.w += w1 * u10.w;
        s1b.x += w1 * u11.x; s1b.y += w1 * u11.y; s1b.z += w1 * u11.z; s1b.w += w1 * u11.w;
    }
    if (e < end) {
        uint2 p0 = g_epack[e];
        float w0 = __uint_as_float(p0.y);
        const float4* q0 = (const float4*)(h + (size_t)p0.x * F);
        float4 u00 = q0[lane], u01 = q0[lane + 32];
        s0a.x += w0 * u00.x; s0a.y += w0 * u00.y; s0a.z += w0 * u00.z; s0a.w += w0 * u00.w;
        s0b.x += w0 * u01.x; s0b.y += w0 * u01.y; s0b.z += w0 * u01.z; s0b.w += w0 * u01.w;
    }

    float di = g_dinv[dst], s = di * di;
    const float4* hd = (const float4*)(h + (size_t)dst * F);
    const float4* bp = (const float4*)bias;
    float4 u0 = hd[lane], u1 = hd[lane + 32];
    float4 b0 = bp[lane], b1 = bp[lane + 32];
    float4 o0, o1;
    o0.x = fmaxf(b0.x + s * u0.x + s0a.x + s1a.x, 0.f);
    o0.y = fmaxf(b0.y + s * u0.y + s0a.y + s1a.y, 0.f);
    o0.z = fmaxf(b0.z + s * u0.z + s0a.z + s1a.z, 0.f);
    o0.w = fmaxf(b0.w + s * u0.w + s0a.w + s1a.w, 0.f);
    o1.x = fmaxf(b1.x + s * u1.x + s0b.x + s1b.x, 0.f);
    o1.y = fmaxf(b1.y + s * u1.y + s0b.y + s1b.y, 0.f);
    o1.z = fmaxf(b1.z + s * u1.z + s0b.z + s1b.z, 0.f);
    o1.w = fmaxf(b1.w + s * u1.w + s0b.w + s1b.w, 0.f);

    if (MODE == 0) {
        float4* ap = (float4*)(AGGF + (size_t)dst * F);
        ap[lane] = o0;
        ap[lane + 32] = o1;
    } else {
        BF16 h0 = __float2bfloat16_rn(o0.x), h1 = __float2bfloat16_rn(o0.y);
        BF16 h2 = __float2bfloat16_rn(o0.z), h3 = __float2bfloat16_rn(o0.w);
        BF16 l0 = __float2bfloat16_rn(o0.x - __bfloat162float(h0));
        BF16 l1 = __float2bfloat16_rn(o0.y - __bfloat162float(h1));
        BF16 l2 = __float2bfloat16_rn(o0.z - __bfloat162float(h2));
        BF16 l3 = __float2bfloat16_rn(o0.w - __bfloat162float(h3));
        BF16 h4 = __float2bfloat16_rn(o1.x), h5 = __float2bfloat16_rn(o1.y);
        BF16 h6 = __float2bfloat16_rn(o1.z), h7 = __float2bfloat16_rn(o1.w);
        BF16 l4 = __float2bfloat16_rn(o1.x - __bfloat162float(h4));
        BF16 l5 = __float2bfloat16_rn(o1.y - __bfloat162float(h5));
        BF16 l6 = __float2bfloat16_rn(o1.z - __bfloat162float(h6));
        BF16 l7 = __float2bfloat16_rn(o1.w - __bfloat162float(h7));
        uint2* ph = (uint2*)(AHo + (size_t)dst * F);
        uint2* pl = (uint2*)(ALo + (size_t)dst * F);
        ph[lane]      = make_uint2(pk(h0, h1), pk(h2, h3));
        ph[lane + 32] = make_uint2(pk(h4, h5), pk(h6, h7));
        pl[lane]      = make_uint2(pk(l0, l1), pk(l2, l3));
        pl[lane + 32] = make_uint2(pk(l4, l5), pk(l6, l7));
    }
}

// ---------------- BN stats over agg2 (already relu'd) ----------------
__global__ void bn_zero() {
    int f = threadIdx.x;
    g_bnsum[f] = 0.0f;
    g_bnssq[f] = 0.0f;
}

__global__ void bn_stats(const float* __restrict__ agg2, int M, int rows_per_block) {
    int f = threadIdx.x;
    long r0 = blockIdx.x * (long)rows_per_block;
    long r1 = r0 + rows_per_block; if (r1 > M) r1 = M;
    float s = 0.f, ss = 0.f;
    for (long r = r0; r < r1; r++) {
        float v = agg2[r * F + f];
        s += v; ss += v * v;
    }
    atomicAdd(&g_bnsum[f], s);
    atomicAdd(&g_bnssq[f], ss);
}

// ---------------- fused BN + LN ----------------
__global__ void bn_ln_final(const float* __restrict__ agg2,
                            const float* __restrict__ bg, const float* __restrict__ bb,
                            const float* __restrict__ lg, const float* __restrict__ lb,
                            float* __restrict__ out, int M) {
    long r = blockIdx.x;
    int  f = threadIdx.x;
    int  lane = f & 31, wid = f >> 5;
    float invM = 1.0f / (float)M;

    float mu  = g_bnsum[f] * invM;
    float var = g_bnssq[f] * invM - mu * mu;
    float v = agg2[r * F + f];
    float y = (v - mu) * rsqrtf(var + EPSV) * bg[f] + bb[f];

    float s = y, ss = y * y;
#pragma unroll
    for (int o = 16; o > 0; o >>= 1) {
        s  += __shfl_xor_sync(0xffffffffu, s,  o);
        ss += __shfl_xor_sync(0xffffffffu, ss, o);
    }
    __shared__ float reds[8], redss[8];
    if (lane == 0) { reds[wid] = s; redss[wid] = ss; }
    __syncthreads();
    if (wid == 0) {
        float a = lane < 8 ? reds[lane]  : 0.f;
        float b = lane < 8 ? redss[lane] : 0.f;
#pragma unroll
        for (int o = 4; o > 0; o >>= 1) {
            a += __shfl_xor_sync(0xffffffffu, a, o);
            b += __shfl_xor_sync(0xffffffffu, b, o);
        }
        if (lane == 0) { reds[0] = a; redss[0] = b; }
    }
    __syncthreads();
    float lmu  = reds[0]  * (1.0f / F);
    float lvar = redss[0] * (1.0f / F) - lmu * lmu;
    out[r * F + f] = (y - lmu) * rsqrtf(lvar + EPSV) * lg[f] + lb[f];
}

// ---------------- launcher ----------------
extern "C" void kernel_launch(void* const* d_in, const int* in_sizes, int n_in,
                              void* d_out, int out_size) {
    const float* x  = (const float*)d_in[0];
    const void*  ei = d_in[1];
    const float* ew = (const float*)d_in[2];
    const float* W1 = (const float*)d_in[3];
    const float* b1 = (const float*)d_in[4];
    const float* W2 = (const float*)d_in[5];
    const float* b2 = (const float*)d_in[6];
    const float* bg = (const float*)d_in[7];
    const float* bb = (const float*)d_in[8];
    const float* lg = (const float*)d_in[9];
    const float* lb = (const float*)d_in[10];
    float* out = (float*)d_out;

    int  n = in_sizes[0] / NFEAT;            // 50000
    long E = in_sizes[1] / 2;                // 800000
    if (E > E_MAX) E = E_MAX;

    float* h1;   cudaGetSymbolAddress((void**)&h1,   g_h1);
    float* h2;   cudaGetSymbolAddress((void**)&h2,   g_h2);
    float* agg2; cudaGetSymbolAddress((void**)&agg2, g_agg2);
    BF16 *xh, *xl, *a1h, *a1l, *w1h, *w1l, *w2h, *w2l;
    cudaGetSymbolAddress((void**)&xh,  g_xh);
    cudaGetSymbolAddress((void**)&xl,  g_xl);
    cudaGetSymbolAddress((void**)&a1h, g_a1h);
    cudaGetSymbolAddress((void**)&a1l, g_a1l);
    cudaGetSymbolAddress((void**)&w1h, g_w1h);
    cudaGetSymbolAddress((void**)&w1l, g_w1l);
    cudaGetSymbolAddress((void**)&w2h, g_w2h);
    cudaGetSymbolAddress((void**)&w2l, g_w2l);

    cudaFuncSetAttribute(gemm_bf16x3,
                         cudaFuncAttributeMaxDynamicSharedMemorySize, GEMM_DSMEM);

    int eb = (int)((E + 255) / 256);
    long x4  = (long)n * NFEAT / 4;
    long w14 = (long)NFEAT * F / 4;
    long w24 = (long)F * F / 4;
    dim3 gg((n + 127) / 128, F / 128);
    int gatherBlocks = (n * 32 + 255) / 256;

    // ---- launches 0-2: converts (gemm1 prereqs) ----
    convert_split<<<(int)((x4 + 255) / 256), 256>>>(x,  xh,  xl,  x4);
    convert_split<<<(int)((w14 + 255) / 256), 256>>>(W1, w1h, w1l, w14);
    convert_split<<<(int)((w24 + 255) / 256), 256>>>(W2, w2h, w2l, w24);

    // ---- launch 3: GEMM1 (positioned at the ncu capture slot) ----
    gemm_bf16x3<<<gg, 256, GEMM_DSMEM>>>(n, F, NFEAT, xh, xl, w1h, w1l, h1);

    // ---- CSR + degree chain (independent of GEMM1) ----
    detect_idx_dtype<<<1, 256>>>((const int*)ei, 1024);
    zero_counts_deg<<<(n + 255) / 256, 256>>>(n);
    histo_deg<<<eb, 256>>>(ei, ew, E);
    compute_dinv<<<(n + 255) / 256, 256>>>(n);
    scan_offsets<<<1, 1024>>>(n);
    scatter_edges<<<eb, 256>>>(ei, ew, E);

    // ---- layer 1 aggregation (writes relu-split bf16 directly) ----
    gather_agg<1><<<gatherBlocks, 256>>>(h1, b1, nullptr, a1h, a1l, n);

    // ---- layer 2 ----
    gemm_bf16x3<<<gg, 256, GEMM_DSMEM>>>(n, F, F, a1h, a1l, w2h, w2l, h2);
    gather_agg<0><<<gatherBlocks, 256>>>(h2, b2, agg2, nullptr, nullptr, n);

    // ---- BN stats + fused BN/LN ----
    bn_zero<<<1, F>>>();
    const int RPB = 128;
    bn_stats<<<(n + RPB - 1) / RPB, F>>>(agg2, n, RPB);
    bn_ln_final<<<n, F>>>(agg2, bg, bb, lg, lb, out, n);
}